// round 2
// baseline (speedup 1.0000x reference)
#include <cuda_runtime.h>
#include <cuda_bf16.h>
#include <math.h>

// ---------------- problem constants ----------------
#define T_TOK 2048
#define HID   2048
#define NH    32
#define NKV   8
#define HD    64
#define EPSV  1e-6f
#define SM_SCALE 0.125f

// ---------------- scratch (device globals; no cudaMalloc allowed) ----------------
__device__ float g_q[T_TOK * NH * HD];     // [2048, 2048]
__device__ float g_k[T_TOK * NKV * HD];    // [2048, 512]
__device__ float g_v[T_TOK * NKV * HD];    // [2048, 512]
__device__ float g_o[T_TOK * NH * HD];     // [2048, 2048] attention out (pre-Wo)
__device__ float g_cos[T_TOK * (HD / 2)];  // [2048, 32]
__device__ float g_sin[T_TOK * (HD / 2)];

// ============================================================================
// 128x128x8 double-buffered SGEMM, 256 threads, 8x8 per thread.
// A is [M,2048] row-major (lda=2048). K loop covers kTotal; for k>=2048 it
// switches to (A2,B2) with row offset k-2048 (hidden+mu fusion).
// ============================================================================
__device__ __forceinline__ void sgemm128(
    const float* __restrict__ A1, const float* __restrict__ A2,
    const float* __restrict__ B1, const float* __restrict__ B2,
    int ldb, float* __restrict__ C, int ldc, int nloc, int kTotal)
{
    const int m0 = blockIdx.y * 128;
    const int t  = threadIdx.x;
    const int tx = t & 15;       // output col group (8 cols)
    const int ty = t >> 4;       // output row group (8 rows)

    __shared__ float As[2][8][128];   // [buf][k][m]
    __shared__ float Bs[2][8][128];   // [buf][k][n]

    const int ar = t >> 1;          // 0..127 (m within tile)
    const int ac = (t & 1) * 4;     // 0 or 4 (k within step)
    const int br = t >> 5;          // 0..7   (k within step)
    const int bc = (t & 31) * 4;    // 0..124 (n within tile)

    float acc[8][8];
#pragma unroll
    for (int i = 0; i < 8; i++)
#pragma unroll
        for (int j = 0; j < 8; j++) acc[i][j] = 0.0f;

    // prologue: load k-step 0 into buffer 0
    {
        float4 a4 = *(const float4*)&A1[(size_t)(m0 + ar) * 2048 + ac];
        float4 b4 = *(const float4*)&B1[(size_t)br * ldb + nloc + bc];
        As[0][ac + 0][ar] = a4.x;
        As[0][ac + 1][ar] = a4.y;
        As[0][ac + 2][ar] = a4.z;
        As[0][ac + 3][ar] = a4.w;
        *(float4*)&Bs[0][br][bc] = b4;
    }
    __syncthreads();

    int cur = 0;
    for (int k0 = 0; k0 < kTotal; k0 += 8) {
        const int kn = k0 + 8;
        const bool has_next = (kn < kTotal);
        float4 a4, b4;
        if (has_next) {
            const float* A = A1;
            const float* B = B1;
            int ko = kn;
            if (kn >= 2048) { A = A2; B = B2; ko = kn - 2048; }
            a4 = *(const float4*)&A[(size_t)(m0 + ar) * 2048 + ko + ac];
            b4 = *(const float4*)&B[(size_t)(ko + br) * ldb + nloc + bc];
        }

#pragma unroll
        for (int k = 0; k < 8; k++) {
            float4 a0 = *(const float4*)&As[cur][k][ty * 8];
            float4 a1 = *(const float4*)&As[cur][k][ty * 8 + 4];
            float4 b0 = *(const float4*)&Bs[cur][k][tx * 8];
            float4 b1 = *(const float4*)&Bs[cur][k][tx * 8 + 4];
            float a[8] = {a0.x, a0.y, a0.z, a0.w, a1.x, a1.y, a1.z, a1.w};
            float b[8] = {b0.x, b0.y, b0.z, b0.w, b1.x, b1.y, b1.z, b1.w};
#pragma unroll
            for (int i = 0; i < 8; i++)
#pragma unroll
                for (int j = 0; j < 8; j++)
                    acc[i][j] = fmaf(a[i], b[j], acc[i][j]);
        }

        if (has_next) {
            const int nxt = cur ^ 1;
            As[nxt][ac + 0][ar] = a4.x;
            As[nxt][ac + 1][ar] = a4.y;
            As[nxt][ac + 2][ar] = a4.z;
            As[nxt][ac + 3][ar] = a4.w;
            *(float4*)&Bs[nxt][br][bc] = b4;
            __syncthreads();
            cur = nxt;
        }
    }

#pragma unroll
    for (int i = 0; i < 8; i++) {
        float4 c0 = {acc[i][0], acc[i][1], acc[i][2], acc[i][3]};
        float4 c1 = {acc[i][4], acc[i][5], acc[i][6], acc[i][7]};
        float* crow = &C[(size_t)(m0 + ty * 8 + i) * ldc + nloc + tx * 8];
        *(float4*)crow       = c0;
        *(float4*)(crow + 4) = c1;
    }
}

// ---- QKV projection: q = hidden@Wq + mu@Wmq (and k,v analogues), fused K=4096 ----
// grid: (24, 16) — column tiles: [0,16)=q, [16,20)=k, [20,24)=v
__global__ void __launch_bounds__(256) qkv_gemm_kernel(
    const float* __restrict__ hidden, const float* __restrict__ mu,
    const float* __restrict__ Wq, const float* __restrict__ Wk, const float* __restrict__ Wv,
    const float* __restrict__ Wmq, const float* __restrict__ Wmk, const float* __restrict__ Wmv)
{
    const int n0 = blockIdx.x * 128;
    const float* B1;
    const float* B2;
    float* C;
    int ldb, nloc;
    if (n0 < 2048)      { B1 = Wq; B2 = Wmq; C = g_q; ldb = 2048; nloc = n0;        }
    else if (n0 < 2560) { B1 = Wk; B2 = Wmk; C = g_k; ldb = 512;  nloc = n0 - 2048; }
    else                { B1 = Wv; B2 = Wmv; C = g_v; ldb = 512;  nloc = n0 - 2560; }
    sgemm128(hidden, mu, B1, B2, ldb, C, ldb, nloc, 4096);
}

// ---- output projection: out = g_o @ Wo ----
__global__ void __launch_bounds__(256) out_gemm_kernel(const float* __restrict__ Wo,
                                                       float* __restrict__ out)
{
    sgemm128(g_o, g_o, Wo, Wo, 2048, out, 2048, blockIdx.x * 128, 2048);
}

// ============================================================================
// RoPE tables in double precision (one-time, tiny)
// ============================================================================
__global__ void rope_table_kernel(const int* __restrict__ positions)
{
    int idx = blockIdx.x * blockDim.x + threadIdx.x;   // t*32 + i
    if (idx >= T_TOK * 32) return;
    int t = idx >> 5;
    int i = idx & 31;
    double invf = pow(10000.0, -(double)i / 32.0);
    double fd   = (double)positions[t] * invf;
    g_cos[idx] = (float)cos(fd);
    g_sin[idx] = (float)sin(fd);
}

// ============================================================================
// Fused RMSNorm + RoPE for q (32 heads) and k (8 heads). One warp per (t, head).
// ============================================================================
__global__ void norm_rope_kernel(const float* __restrict__ qw,
                                 const float* __restrict__ kw)
{
    int warpId = blockIdx.x * (blockDim.x >> 5) + (threadIdx.x >> 5);
    int lane   = threadIdx.x & 31;
    if (warpId >= T_TOK * (NH + NKV)) return;
    int t  = warpId / (NH + NKV);
    int hh = warpId % (NH + NKV);

    float* buf;
    int ld, col;
    const float* w;
    if (hh < NH) { buf = g_q; ld = NH * HD;  col = hh * HD;        w = qw; }
    else         { buf = g_k; ld = NKV * HD; col = (hh - NH) * HD; w = kw; }

    float x0 = buf[(size_t)t * ld + col + lane];
    float x1 = buf[(size_t)t * ld + col + 32 + lane];
    float ss = x0 * x0 + x1 * x1;
#pragma unroll
    for (int o = 16; o > 0; o >>= 1) ss += __shfl_xor_sync(0xffffffff, ss, o);
    float inv = rsqrtf(ss * (1.0f / 64.0f) + EPSV);
    x0 *= inv * w[lane];
    x1 *= inv * w[lane + 32];

    float c = g_cos[t * 32 + lane];
    float s = g_sin[t * 32 + lane];
    buf[(size_t)t * ld + col + lane]      = x0 * c - x1 * s;
    buf[(size_t)t * ld + col + 32 + lane] = x1 * c + x0 * s;
}

// ============================================================================
// Causal flash attention. grid: (32 q-tiles, NH), block 256, 4x4 per thread.
// Q,K stored d-major in smem; P stored col-major; softmax fully in registers.
// ============================================================================
#define PLD 68                                   // padded stride (16B aligned)
#define FLASH_SMEM (4 * 64 * PLD * (int)sizeof(float))

__global__ void __launch_bounds__(256) flash_kernel()
{
    extern __shared__ float sm[];
    float* Qt = sm;                 // Qt[d*PLD + row]  = Q[row][d]
    float* Kt = sm + 64 * PLD;      // Kt[d*PLD + col]  = K[col][d]
    float* Vs = sm + 2 * 64 * PLD;  // Vs[kk*PLD + c]   = V[kk][c]
    float* Pt = sm + 3 * 64 * PLD;  // Pt[col*PLD + row] = P[row][col]

    const int qt  = blockIdx.x;
    const int h   = blockIdx.y;
    const int kvh = h >> 2;              // GQA: 4 q-heads share a kv head
    const int t   = threadIdx.x;
    const int tx  = t & 15;
    const int ty  = t >> 4;
    const int q0  = qt * 64;

    // load Q tile transposed (d-major)
#pragma unroll
    for (int u = 0; u < 4; u++) {
        int idx = u * 256 + t;
        int r = idx >> 4, cq = (idx & 15) * 4;
        float4 q4 = *(const float4*)&g_q[(size_t)(q0 + r) * (NH * HD) + h * HD + cq];
        Qt[(cq + 0) * PLD + r] = q4.x;
        Qt[(cq + 1) * PLD + r] = q4.y;
        Qt[(cq + 2) * PLD + r] = q4.z;
        Qt[(cq + 3) * PLD + r] = q4.w;
    }

    float acc[4][4];
    float m[4], l[4];
#pragma unroll
    for (int i = 0; i < 4; i++) {
        m[i] = -1e30f; l[i] = 0.0f;
#pragma unroll
        for (int j = 0; j < 4; j++) acc[i][j] = 0.0f;
    }

    __syncthreads();

    for (int kt = 0; kt <= qt; kt++) {
        // load K (transposed) and V tiles
#pragma unroll
        for (int u = 0; u < 4; u++) {
            int idx = u * 256 + t;
            int r = idx >> 4, cq = (idx & 15) * 4;
            size_t gi = (size_t)(kt * 64 + r) * (NKV * HD) + kvh * HD + cq;
            float4 k4 = *(const float4*)&g_k[gi];
            float4 v4 = *(const float4*)&g_v[gi];
            Kt[(cq + 0) * PLD + r] = k4.x;
            Kt[(cq + 1) * PLD + r] = k4.y;
            Kt[(cq + 2) * PLD + r] = k4.z;
            Kt[(cq + 3) * PLD + r] = k4.w;
            *(float4*)&Vs[r * PLD + cq] = v4;
        }
        __syncthreads();

        // S = Q @ K^T : pure float4 LDS
        float s[4][4];
#pragma unroll
        for (int i = 0; i < 4; i++)
#pragma unroll
            for (int j = 0; j < 4; j++) s[i][j] = 0.0f;

#pragma unroll 8
        for (int d = 0; d < 64; d++) {
            float4 av = *(const float4*)&Qt[d * PLD + ty * 4];
            float4 bv = *(const float4*)&Kt[d * PLD + tx * 4];
            float a[4] = {av.x, av.y, av.z, av.w};
            float b[4] = {bv.x, bv.y, bv.z, bv.w};
#pragma unroll
            for (int i = 0; i < 4; i++)
#pragma unroll
                for (int j = 0; j < 4; j++)
                    s[i][j] = fmaf(a[i], b[j], s[i][j]);
        }

        // scale + causal mask (only diagonal tile)
        const bool diag = (kt == qt);
#pragma unroll
        for (int i = 0; i < 4; i++)
#pragma unroll
            for (int j = 0; j < 4; j++) {
                float v = s[i][j] * SM_SCALE;
                if (diag && (tx * 4 + j) > (ty * 4 + i)) v = -1e30f;
                s[i][j] = v;
            }

        // in-register online softmax (reduce across the 16 lanes sharing a row)
#pragma unroll
        for (int i = 0; i < 4; i++) {
            float rmax = fmaxf(fmaxf(s[i][0], s[i][1]), fmaxf(s[i][2], s[i][3]));
#pragma unroll
            for (int o = 8; o > 0; o >>= 1)
                rmax = fmaxf(rmax, __shfl_xor_sync(0xffffffff, rmax, o));
            float mnew  = fmaxf(m[i], rmax);
            float alpha = __expf(m[i] - mnew);
            m[i] = mnew;
            float rsum = 0.0f;
#pragma unroll
            for (int j = 0; j < 4; j++) {
                float p = __expf(s[i][j] - mnew);
                s[i][j] = p;
                rsum += p;
            }
#pragma unroll
            for (int o = 8; o > 0; o >>= 1)
                rsum += __shfl_xor_sync(0xffffffff, rsum, o);
            l[i] = l[i] * alpha + rsum;
#pragma unroll
            for (int j = 0; j < 4; j++) acc[i][j] *= alpha;
        }

        // write P transposed: Pt[col][row]
#pragma unroll
        for (int j = 0; j < 4; j++) {
            float4 pc = {s[0][j], s[1][j], s[2][j], s[3][j]};
            *(float4*)&Pt[(tx * 4 + j) * PLD + ty * 4] = pc;
        }
        __syncthreads();

        // O += P @ V : pure float4 LDS
#pragma unroll 8
        for (int kk = 0; kk < 64; kk++) {
            float4 pv = *(const float4*)&Pt[kk * PLD + ty * 4];
            float4 vv = *(const float4*)&Vs[kk * PLD + tx * 4];
            float p[4] = {pv.x, pv.y, pv.z, pv.w};
            float v[4] = {vv.x, vv.y, vv.z, vv.w};
#pragma unroll
            for (int i = 0; i < 4; i++)
#pragma unroll
                for (int j = 0; j < 4; j++)
                    acc[i][j] = fmaf(p[i], v[j], acc[i][j]);
        }
        __syncthreads();   // Kt/Vs/Pt free for next iteration
    }

    // normalize and write
#pragma unroll
    for (int i = 0; i < 4; i++) {
        float inv = 1.0f / l[i];
        float4 c = {acc[i][0] * inv, acc[i][1] * inv, acc[i][2] * inv, acc[i][3] * inv};
        *(float4*)&g_o[(size_t)(q0 + ty * 4 + i) * (NH * HD) + h * HD + tx * 4] = c;
    }
}

// ============================================================================
// launch
// ============================================================================
extern "C" void kernel_launch(void* const* d_in, const int* in_sizes, int n_in,
                              void* d_out, int out_size)
{
    const float* hidden = (const float*)d_in[0];
    const float* mu     = (const float*)d_in[1];
    const float* Wq     = (const float*)d_in[2];
    const float* Wk     = (const float*)d_in[3];
    const float* Wv     = (const float*)d_in[4];
    const float* Wo     = (const float*)d_in[5];
    const float* Wmq    = (const float*)d_in[6];
    const float* Wmk    = (const float*)d_in[7];
    const float* Wmv    = (const float*)d_in[8];
    const float* qnw    = (const float*)d_in[9];
    const float* knw    = (const float*)d_in[10];
    const int*   pos    = (const int*)d_in[11];
    float* out          = (float*)d_out;

    cudaFuncSetAttribute(flash_kernel, cudaFuncAttributeMaxDynamicSharedMemorySize, FLASH_SMEM);

    // QKV projection (fused hidden+mu, K=4096; N regions: q|k|v)
    qkv_gemm_kernel<<<dim3(24, 16), 256>>>(hidden, mu, Wq, Wk, Wv, Wmq, Wmk, Wmv);

    // RoPE tables (double precision, tiny)
    rope_table_kernel<<<(T_TOK * 32 + 255) / 256, 256>>>(pos);

    // RMSNorm + RoPE on q and k heads (one warp per (token, head))
    norm_rope_kernel<<<(T_TOK * (NH + NKV) + 7) / 8, 256>>>(qnw, knw);

    // causal flash attention
    flash_kernel<<<dim3(T_TOK / 64, NH), 256, FLASH_SMEM>>>();

    // output projection
    out_gemm_kernel<<<dim3(16, 16), 256>>>(Wo, out);
}

// round 3
// speedup vs baseline: 1.6278x; 1.6278x over previous
#include <cuda_runtime.h>
#include <cuda_bf16.h>
#include <math.h>

// ---------------- problem constants ----------------
#define T_TOK 2048
#define HID   2048
#define NH    32
#define NKV   8
#define HD    64
#define EPSV  1e-6f
#define SM_SCALE 0.125f

// ---------------- scratch (device globals; no cudaMalloc allowed) ----------------
__device__ float g_q[T_TOK * NH * HD];     // [2048, 2048]
__device__ float g_k[T_TOK * NKV * HD];    // [2048, 512]
__device__ float g_v[T_TOK * NKV * HD];    // [2048, 512]
__device__ float g_o[T_TOK * NH * HD];     // [2048, 2048] attention out (pre-Wo)
__device__ float g_cos[T_TOK * (HD / 2)];  // [2048, 32]
__device__ float g_sin[T_TOK * (HD / 2)];

// ============================================================================
// 128x128x16 double-buffered SGEMM, 512 threads, 8x4 per thread.
// a-reads are warp-broadcast, b-reads are conflict-free consecutive float4.
// A is [M,2048] row-major. K loop covers kTotal; for k>=2048 switches to
// (A2,B2) with row offset k-2048 (hidden+mu fusion).
// ============================================================================
__device__ __forceinline__ void sgemm128(
    const float* __restrict__ A1, const float* __restrict__ A2,
    const float* __restrict__ B1, const float* __restrict__ B2,
    int ldb, float* __restrict__ C, int ldc, int nloc, int kTotal)
{
    const int m0   = blockIdx.y * 128;
    const int t    = threadIdx.x;     // 0..511
    const int lane = t & 31;
    const int warp = t >> 5;          // 0..15

    __shared__ float As[2][16][128];  // [buf][k][m]
    __shared__ float Bs[2][16][128];  // [buf][k][n]

    const int ar = t >> 2;            // 0..127 (m within tile)
    const int ac = (t & 3) * 4;       // 0,4,8,12 (k within step)
    const int br = t >> 5;            // 0..15  (k within step)
    const int bc = (t & 31) * 4;      // 0..124 (n within tile)

    float acc[8][4];
#pragma unroll
    for (int i = 0; i < 8; i++)
#pragma unroll
        for (int j = 0; j < 4; j++) acc[i][j] = 0.0f;

    // prologue: k-step 0 into buffer 0
    {
        float4 a4 = *(const float4*)&A1[(size_t)(m0 + ar) * 2048 + ac];
        float4 b4 = *(const float4*)&B1[(size_t)br * ldb + nloc + bc];
        As[0][ac + 0][ar] = a4.x;
        As[0][ac + 1][ar] = a4.y;
        As[0][ac + 2][ar] = a4.z;
        As[0][ac + 3][ar] = a4.w;
        *(float4*)&Bs[0][br][bc] = b4;
    }
    __syncthreads();

    int cur = 0;
    for (int k0 = 0; k0 < kTotal; k0 += 16) {
        const int kn = k0 + 16;
        const bool has_next = (kn < kTotal);
        float4 a4, b4;
        if (has_next) {
            const float* A = A1;
            const float* B = B1;
            int ko = kn;
            if (kn >= 2048) { A = A2; B = B2; ko = kn - 2048; }
            a4 = *(const float4*)&A[(size_t)(m0 + ar) * 2048 + ko + ac];
            b4 = *(const float4*)&B[(size_t)(ko + br) * ldb + nloc + bc];
        }

#pragma unroll
        for (int k = 0; k < 16; k++) {
            float4 av0 = *(const float4*)&As[cur][k][warp * 8];      // broadcast
            float4 av1 = *(const float4*)&As[cur][k][warp * 8 + 4];  // broadcast
            float4 bv  = *(const float4*)&Bs[cur][k][lane * 4];      // conflict-free
            float a[8] = {av0.x, av0.y, av0.z, av0.w, av1.x, av1.y, av1.z, av1.w};
            float b[4] = {bv.x, bv.y, bv.z, bv.w};
#pragma unroll
            for (int i = 0; i < 8; i++)
#pragma unroll
                for (int j = 0; j < 4; j++)
                    acc[i][j] = fmaf(a[i], b[j], acc[i][j]);
        }

        if (has_next) {
            const int nxt = cur ^ 1;
            As[nxt][ac + 0][ar] = a4.x;
            As[nxt][ac + 1][ar] = a4.y;
            As[nxt][ac + 2][ar] = a4.z;
            As[nxt][ac + 3][ar] = a4.w;
            *(float4*)&Bs[nxt][br][bc] = b4;
            __syncthreads();
            cur = nxt;
        }
    }

    // epilogue: warp w owns rows [8w, 8w+8), lane owns 4 consecutive cols
#pragma unroll
    for (int i = 0; i < 8; i++) {
        float4 c = {acc[i][0], acc[i][1], acc[i][2], acc[i][3]};
        *(float4*)&C[(size_t)(m0 + warp * 8 + i) * ldc + nloc + lane * 4] = c;
    }
}

// ---- QKV projection: q = hidden@Wq + mu@Wmq (and k,v analogues), fused K=4096 ----
// grid: (24, 16) — column tiles: [0,16)=q, [16,20)=k, [20,24)=v
__global__ void __launch_bounds__(512) qkv_gemm_kernel(
    const float* __restrict__ hidden, const float* __restrict__ mu,
    const float* __restrict__ Wq, const float* __restrict__ Wk, const float* __restrict__ Wv,
    const float* __restrict__ Wmq, const float* __restrict__ Wmk, const float* __restrict__ Wmv)
{
    const int n0 = blockIdx.x * 128;
    const float* B1;
    const float* B2;
    float* C;
    int ldb, nloc;
    if (n0 < 2048)      { B1 = Wq; B2 = Wmq; C = g_q; ldb = 2048; nloc = n0;        }
    else if (n0 < 2560) { B1 = Wk; B2 = Wmk; C = g_k; ldb = 512;  nloc = n0 - 2048; }
    else                { B1 = Wv; B2 = Wmv; C = g_v; ldb = 512;  nloc = n0 - 2560; }
    sgemm128(hidden, mu, B1, B2, ldb, C, ldb, nloc, 4096);
}

// ---- output projection: out = g_o @ Wo ----
__global__ void __launch_bounds__(512) out_gemm_kernel(const float* __restrict__ Wo,
                                                       float* __restrict__ out)
{
    sgemm128(g_o, g_o, Wo, Wo, 2048, out, 2048, blockIdx.x * 128, 2048);
}

// ============================================================================
// RoPE tables in double precision (one-time, tiny)
// ============================================================================
__global__ void rope_table_kernel(const int* __restrict__ positions)
{
    int idx = blockIdx.x * blockDim.x + threadIdx.x;   // t*32 + i
    if (idx >= T_TOK * 32) return;
    int t = idx >> 5;
    int i = idx & 31;
    double invf = pow(10000.0, -(double)i / 32.0);
    double fd   = (double)positions[t] * invf;
    g_cos[idx] = (float)cos(fd);
    g_sin[idx] = (float)sin(fd);
}

// ============================================================================
// Fused RMSNorm + RoPE for q (32 heads) and k (8 heads). One warp per (t, head).
// ============================================================================
__global__ void norm_rope_kernel(const float* __restrict__ qw,
                                 const float* __restrict__ kw)
{
    int warpId = blockIdx.x * (blockDim.x >> 5) + (threadIdx.x >> 5);
    int lane   = threadIdx.x & 31;
    if (warpId >= T_TOK * (NH + NKV)) return;
    int t  = warpId / (NH + NKV);
    int hh = warpId % (NH + NKV);

    float* buf;
    int ld, col;
    const float* w;
    if (hh < NH) { buf = g_q; ld = NH * HD;  col = hh * HD;        w = qw; }
    else         { buf = g_k; ld = NKV * HD; col = (hh - NH) * HD; w = kw; }

    float x0 = buf[(size_t)t * ld + col + lane];
    float x1 = buf[(size_t)t * ld + col + 32 + lane];
    float ss = x0 * x0 + x1 * x1;
#pragma unroll
    for (int o = 16; o > 0; o >>= 1) ss += __shfl_xor_sync(0xffffffff, ss, o);
    float inv = rsqrtf(ss * (1.0f / 64.0f) + EPSV);
    x0 *= inv * w[lane];
    x1 *= inv * w[lane + 32];

    float c = g_cos[t * 32 + lane];
    float s = g_sin[t * 32 + lane];
    buf[(size_t)t * ld + col + lane]      = x0 * c - x1 * s;
    buf[(size_t)t * ld + col + 32 + lane] = x1 * c + x0 * s;
}

// ============================================================================
// Causal flash attention. grid: (32 q-tiles, NH), block 256, 4x4 per thread.
// Q,K stored d-major in smem; P stored col-major; softmax fully in registers.
// ============================================================================
#define PLD 68                                   // padded stride (16B aligned)
#define FLASH_SMEM (4 * 64 * PLD * (int)sizeof(float))

__global__ void __launch_bounds__(256) flash_kernel()
{
    extern __shared__ float sm[];
    float* Qt = sm;                 // Qt[d*PLD + row]  = Q[row][d]
    float* Kt = sm + 64 * PLD;      // Kt[d*PLD + col]  = K[col][d]
    float* Vs = sm + 2 * 64 * PLD;  // Vs[kk*PLD + c]   = V[kk][c]
    float* Pt = sm + 3 * 64 * PLD;  // Pt[col*PLD + row] = P[row][col]

    const int qt  = blockIdx.x;
    const int h   = blockIdx.y;
    const int kvh = h >> 2;              // GQA: 4 q-heads share a kv head
    const int t   = threadIdx.x;
    const int tx  = t & 15;
    const int ty  = t >> 4;
    const int q0  = qt * 64;

    // load Q tile transposed (d-major)
#pragma unroll
    for (int u = 0; u < 4; u++) {
        int idx = u * 256 + t;
        int r = idx >> 4, cq = (idx & 15) * 4;
        float4 q4 = *(const float4*)&g_q[(size_t)(q0 + r) * (NH * HD) + h * HD + cq];
        Qt[(cq + 0) * PLD + r] = q4.x;
        Qt[(cq + 1) * PLD + r] = q4.y;
        Qt[(cq + 2) * PLD + r] = q4.z;
        Qt[(cq + 3) * PLD + r] = q4.w;
    }

    float acc[4][4];
    float m[4], l[4];
#pragma unroll
    for (int i = 0; i < 4; i++) {
        m[i] = -1e30f; l[i] = 0.0f;
#pragma unroll
        for (int j = 0; j < 4; j++) acc[i][j] = 0.0f;
    }

    __syncthreads();

    for (int kt = 0; kt <= qt; kt++) {
        // load K (transposed) and V tiles
#pragma unroll
        for (int u = 0; u < 4; u++) {
            int idx = u * 256 + t;
            int r = idx >> 4, cq = (idx & 15) * 4;
            size_t gi = (size_t)(kt * 64 + r) * (NKV * HD) + kvh * HD + cq;
            float4 k4 = *(const float4*)&g_k[gi];
            float4 v4 = *(const float4*)&g_v[gi];
            Kt[(cq + 0) * PLD + r] = k4.x;
            Kt[(cq + 1) * PLD + r] = k4.y;
            Kt[(cq + 2) * PLD + r] = k4.z;
            Kt[(cq + 3) * PLD + r] = k4.w;
            *(float4*)&Vs[r * PLD + cq] = v4;
        }
        __syncthreads();

        // S = Q @ K^T : pure float4 LDS
        float s[4][4];
#pragma unroll
        for (int i = 0; i < 4; i++)
#pragma unroll
            for (int j = 0; j < 4; j++) s[i][j] = 0.0f;

#pragma unroll 8
        for (int d = 0; d < 64; d++) {
            float4 av = *(const float4*)&Qt[d * PLD + ty * 4];
            float4 bv = *(const float4*)&Kt[d * PLD + tx * 4];
            float a[4] = {av.x, av.y, av.z, av.w};
            float b[4] = {bv.x, bv.y, bv.z, bv.w};
#pragma unroll
            for (int i = 0; i < 4; i++)
#pragma unroll
                for (int j = 0; j < 4; j++)
                    s[i][j] = fmaf(a[i], b[j], s[i][j]);
        }

        // scale + causal mask (only diagonal tile)
        const bool diag = (kt == qt);
#pragma unroll
        for (int i = 0; i < 4; i++)
#pragma unroll
            for (int j = 0; j < 4; j++) {
                float v = s[i][j] * SM_SCALE;
                if (diag && (tx * 4 + j) > (ty * 4 + i)) v = -1e30f;
                s[i][j] = v;
            }

        // in-register online softmax (reduce across the 16 lanes sharing a row)
#pragma unroll
        for (int i = 0; i < 4; i++) {
            float rmax = fmaxf(fmaxf(s[i][0], s[i][1]), fmaxf(s[i][2], s[i][3]));
#pragma unroll
            for (int o = 8; o > 0; o >>= 1)
                rmax = fmaxf(rmax, __shfl_xor_sync(0xffffffff, rmax, o));
            float mnew  = fmaxf(m[i], rmax);
            float alpha = __expf(m[i] - mnew);
            m[i] = mnew;
            float rsum = 0.0f;
#pragma unroll
            for (int j = 0; j < 4; j++) {
                float p = __expf(s[i][j] - mnew);
                s[i][j] = p;
                rsum += p;
            }
#pragma unroll
            for (int o = 8; o > 0; o >>= 1)
                rsum += __shfl_xor_sync(0xffffffff, rsum, o);
            l[i] = l[i] * alpha + rsum;
#pragma unroll
            for (int j = 0; j < 4; j++) acc[i][j] *= alpha;
        }

        // write P transposed: Pt[col][row]
#pragma unroll
        for (int j = 0; j < 4; j++) {
            float4 pc = {s[0][j], s[1][j], s[2][j], s[3][j]};
            *(float4*)&Pt[(tx * 4 + j) * PLD + ty * 4] = pc;
        }
        __syncthreads();

        // O += P @ V : pure float4 LDS
#pragma unroll 8
        for (int kk = 0; kk < 64; kk++) {
            float4 pv = *(const float4*)&Pt[kk * PLD + ty * 4];
            float4 vv = *(const float4*)&Vs[kk * PLD + tx * 4];
            float p[4] = {pv.x, pv.y, pv.z, pv.w};
            float v[4] = {vv.x, vv.y, vv.z, vv.w};
#pragma unroll
            for (int i = 0; i < 4; i++)
#pragma unroll
                for (int j = 0; j < 4; j++)
                    acc[i][j] = fmaf(p[i], v[j], acc[i][j]);
        }
        __syncthreads();   // Kt/Vs/Pt free for next iteration
    }

    // normalize and write
#pragma unroll
    for (int i = 0; i < 4; i++) {
        float inv = 1.0f / l[i];
        float4 c = {acc[i][0] * inv, acc[i][1] * inv, acc[i][2] * inv, acc[i][3] * inv};
        *(float4*)&g_o[(size_t)(q0 + ty * 4 + i) * (NH * HD) + h * HD + tx * 4] = c;
    }
}

// ============================================================================
// launch
// ============================================================================
extern "C" void kernel_launch(void* const* d_in, const int* in_sizes, int n_in,
                              void* d_out, int out_size)
{
    const float* hidden = (const float*)d_in[0];
    const float* mu     = (const float*)d_in[1];
    const float* Wq     = (const float*)d_in[2];
    const float* Wk     = (const float*)d_in[3];
    const float* Wv     = (const float*)d_in[4];
    const float* Wo     = (const float*)d_in[5];
    const float* Wmq    = (const float*)d_in[6];
    const float* Wmk    = (const float*)d_in[7];
    const float* Wmv    = (const float*)d_in[8];
    const float* qnw    = (const float*)d_in[9];
    const float* knw    = (const float*)d_in[10];
    const int*   pos    = (const int*)d_in[11];
    float* out          = (float*)d_out;

    cudaFuncSetAttribute(flash_kernel, cudaFuncAttributeMaxDynamicSharedMemorySize, FLASH_SMEM);

    // QKV projection (fused hidden+mu, K=4096; N regions: q|k|v)
    qkv_gemm_kernel<<<dim3(24, 16), 512>>>(hidden, mu, Wq, Wk, Wv, Wmq, Wmk, Wmv);

    // RoPE tables (double precision, tiny)
    rope_table_kernel<<<(T_TOK * 32 + 255) / 256, 256>>>(pos);

    // RMSNorm + RoPE on q and k heads (one warp per (token, head))
    norm_rope_kernel<<<(T_TOK * (NH + NKV) + 7) / 8, 256>>>(qnw, knw);

    // causal flash attention
    flash_kernel<<<dim3(T_TOK / 64, NH), 256, FLASH_SMEM>>>();

    // output projection
    out_gemm_kernel<<<dim3(16, 16), 512>>>(Wo, out);
}

// round 5
// speedup vs baseline: 2.8924x; 1.7769x over previous
#include <cuda_runtime.h>
#include <cuda_bf16.h>
#include <math.h>
#include <stdint.h>

// ---------------- problem constants ----------------
#define T_TOK 2048
#define HID   2048
#define NH    32
#define NKV   8
#define HD    64
#define EPSV  1e-6f
#define SM_SCALE 0.125f

// ---------------- fp32 scratch ----------------
__device__ float g_q[T_TOK * NH * HD];     // [2048, 2048]
__device__ float g_k[T_TOK * NKV * HD];    // [2048, 512]
__device__ float g_v[T_TOK * NKV * HD];    // [2048, 512]
__device__ float g_o[T_TOK * NH * HD];     // [2048, 2048]
__device__ float g_cos[T_TOK * (HD / 2)];
__device__ float g_sin[T_TOK * (HD / 2)];

// ---------------- bf16 split scratch ----------------
__device__ __nv_bfloat16 g_Ah[T_TOK * 4096];   // [2048,4096] = [hidden|mu] hi
__device__ __nv_bfloat16 g_Al[T_TOK * 4096];   // lo
__device__ __nv_bfloat16 g_Bh[4096 * 3072];    // [[Wq|Wk|Wv];[Wmq|Wmk|Wmv]] hi
__device__ __nv_bfloat16 g_Bl[4096 * 3072];
__device__ __nv_bfloat16 g_Oh[T_TOK * 2048];   // g_o hi/lo
__device__ __nv_bfloat16 g_Ol[T_TOK * 2048];
__device__ __nv_bfloat16 g_Wh[2048 * 2048];    // Wo hi/lo
__device__ __nv_bfloat16 g_Wl[2048 * 2048];

// ============================================================================
// PTX helpers
// ============================================================================
__device__ __forceinline__ uint32_t smem_u32(const void* p) {
    return (uint32_t)__cvta_generic_to_shared(p);
}
__device__ __forceinline__ void ldsm4(uint32_t (&r)[4], uint32_t addr) {
    asm volatile("ldmatrix.sync.aligned.m8n8.x4.shared.b16 {%0,%1,%2,%3}, [%4];"
                 : "=r"(r[0]), "=r"(r[1]), "=r"(r[2]), "=r"(r[3]) : "r"(addr));
}
__device__ __forceinline__ void ldsm4t(uint32_t (&r)[4], uint32_t addr) {
    asm volatile("ldmatrix.sync.aligned.m8n8.x4.trans.shared.b16 {%0,%1,%2,%3}, [%4];"
                 : "=r"(r[0]), "=r"(r[1]), "=r"(r[2]), "=r"(r[3]) : "r"(addr));
}
__device__ __forceinline__ void mma16816(float (&c)[4], const uint32_t (&a)[4],
                                         uint32_t b0, uint32_t b1) {
    asm volatile("mma.sync.aligned.m16n8k16.row.col.f32.bf16.bf16.f32 "
                 "{%0,%1,%2,%3}, {%4,%5,%6,%7}, {%8,%9}, {%0,%1,%2,%3};"
                 : "+f"(c[0]), "+f"(c[1]), "+f"(c[2]), "+f"(c[3])
                 : "r"(a[0]), "r"(a[1]), "r"(a[2]), "r"(a[3]), "r"(b0), "r"(b1));
}
__device__ __forceinline__ void cpasync16(uint32_t dst, const void* src) {
    asm volatile("cp.async.cg.shared.global [%0], [%1], 16;" :: "r"(dst), "l"(src));
}
__device__ __forceinline__ void cp_commit() {
    asm volatile("cp.async.commit_group;" ::: "memory");
}
__device__ __forceinline__ void cp_wait0() {
    asm volatile("cp.async.wait_group 0;" ::: "memory");
}

// ============================================================================
// bf16 split conversion kernels (x = hi + lo)
// ============================================================================
__device__ __forceinline__ uint32_t packh(__nv_bfloat16 a, __nv_bfloat16 b) {
    __nv_bfloat162 v = __halves2bfloat162(a, b);
    return *reinterpret_cast<uint32_t*>(&v);
}
__device__ __forceinline__ void split_store4(__nv_bfloat16* dh, __nv_bfloat16* dl,
                                             size_t off, float4 x) {
    __nv_bfloat16 h0 = __float2bfloat16(x.x);
    __nv_bfloat16 h1 = __float2bfloat16(x.y);
    __nv_bfloat16 h2 = __float2bfloat16(x.z);
    __nv_bfloat16 h3 = __float2bfloat16(x.w);
    __nv_bfloat16 l0 = __float2bfloat16(x.x - __bfloat162float(h0));
    __nv_bfloat16 l1 = __float2bfloat16(x.y - __bfloat162float(h1));
    __nv_bfloat16 l2 = __float2bfloat16(x.z - __bfloat162float(h2));
    __nv_bfloat16 l3 = __float2bfloat16(x.w - __bfloat162float(h3));
    uint2 hv = {packh(h0, h1), packh(h2, h3)};
    uint2 lv = {packh(l0, l1), packh(l2, l3)};
    *reinterpret_cast<uint2*>(dh + off) = hv;
    *reinterpret_cast<uint2*>(dl + off) = lv;
}

// A = [hidden | mu] : [2048, 4096]
__global__ void convert_A_kernel(const float* __restrict__ hidden,
                                 const float* __restrict__ mu) {
    int idx = blockIdx.x * blockDim.x + threadIdx.x;   // per float4
    if (idx >= T_TOK * 1024) return;
    int t = idx >> 10, c4 = idx & 1023;
    float4 x = (c4 < 512) ? ((const float4*)hidden)[t * 512 + c4]
                          : ((const float4*)mu)[t * 512 + c4 - 512];
    split_store4(g_Ah, g_Al, (size_t)t * 4096 + c4 * 4, x);
}

// B : [4096, 3072]; rows 0-2047 = [Wq|Wk|Wv], rows 2048+ = [Wmq|Wmk|Wmv]
__global__ void convert_B_kernel(const float* __restrict__ Wq, const float* __restrict__ Wk,
                                 const float* __restrict__ Wv, const float* __restrict__ Wmq,
                                 const float* __restrict__ Wmk, const float* __restrict__ Wmv) {
    int idx = blockIdx.x * blockDim.x + threadIdx.x;   // per float4
    if (idx >= 4096 * 768) return;
    int k = idx / 768, c4 = idx % 768;
    int n = c4 * 4;
    int kk = k & 2047;
    const float* src;
    size_t off;
    if (n < 2048)      { src = (k < 2048) ? Wq : Wmq; off = (size_t)kk * 2048 + n; }
    else if (n < 2560) { src = (k < 2048) ? Wk : Wmk; off = (size_t)kk * 512 + (n - 2048); }
    else               { src = (k < 2048) ? Wv : Wmv; off = (size_t)kk * 512 + (n - 2560); }
    float4 x = *(const float4*)&src[off];
    split_store4(g_Bh, g_Bl, (size_t)k * 3072 + n, x);
}

__global__ void convert_Wo_kernel(const float* __restrict__ Wo) {
    int idx = blockIdx.x * blockDim.x + threadIdx.x;
    if (idx >= 2048 * 512) return;
    float4 x = ((const float4*)Wo)[idx];
    split_store4(g_Wh, g_Wl, (size_t)idx * 4, x);
}

__global__ void convert_O_kernel() {
    int idx = blockIdx.x * blockDim.x + threadIdx.x;
    if (idx >= 2048 * 512) return;
    float4 x = ((const float4*)g_o)[idx];
    split_store4(g_Oh, g_Ol, (size_t)idx * 4, x);
}

// ============================================================================
// Tensor-core GEMM, 3-term bf16 split. Block 128x128, 8 warps, warp 32x64.
// smem (bf16 units): A pad-stride 40, B pad-stride 136 (conflict-free ldmatrix).
// ============================================================================
#define SM_AH 0
#define SM_AL 10240        // 2*128*40
#define SM_BH 20480
#define SM_BL 29184        // +2*32*136
#define SMEM_GEMM_BYTES (37888 * 2)

__device__ __forceinline__ void gemm_core(
    const __nv_bfloat16* __restrict__ Ah, const __nv_bfloat16* __restrict__ Al, int lda,
    const __nv_bfloat16* __restrict__ Bh, const __nv_bfloat16* __restrict__ Bl, int ldb, int nb,
    float* __restrict__ C, int ldc, int ncBase, int kTotal)
{
    extern __shared__ __nv_bfloat16 smem[];
    __nv_bfloat16* sAh = smem + SM_AH;
    __nv_bfloat16* sAl = smem + SM_AL;
    __nv_bfloat16* sBh = smem + SM_BH;
    __nv_bfloat16* sBl = smem + SM_BL;

    const int t    = threadIdx.x;
    const int lane = t & 31;
    const int warp = t >> 5;
    const int mw   = (warp >> 1) * 32;   // warp m offset in tile
    const int nw   = (warp & 1) * 64;    // warp n offset in tile
    const int m0   = blockIdx.y * 128;

    float acc[2][8][4];
#pragma unroll
    for (int i = 0; i < 2; i++)
#pragma unroll
        for (int j = 0; j < 8; j++)
#pragma unroll
            for (int q = 0; q < 4; q++) acc[i][j][q] = 0.0f;

    // async copy: 8-element (16B) chunks; A tile 128x32 = 512 chunks,
    // B tile 32x128 = 512 chunks; 256 threads x 2 iterations each.
    auto issue = [&](int buf, int k0) {
#pragma unroll
        for (int i = 0; i < 2; i++) {
            const int c  = t + i * 256;           // chunk id 0..511
            const int ra = c >> 2, ca = (c & 3) * 8;    // A: row, k-elem offset
            const size_t ga = (size_t)(m0 + ra) * lda + k0 + ca;
            cpasync16(smem_u32(sAh + buf * 5120 + ra * 40 + ca), Ah + ga);
            cpasync16(smem_u32(sAl + buf * 5120 + ra * 40 + ca), Al + ga);
            const int rb = c >> 4, cb = (c & 15) * 8;   // B: k row, n-elem offset
            const size_t gb = (size_t)(k0 + rb) * ldb + nb + cb;
            cpasync16(smem_u32(sBh + buf * 4352 + rb * 136 + cb), Bh + gb);
            cpasync16(smem_u32(sBl + buf * 4352 + rb * 136 + cb), Bl + gb);
        }
        cp_commit();
    };

    // ldmatrix lane mapping
    const int arf = lane & 15;                          // A row within m16
    const int acf = (lane >> 4) << 3;                   // A k offset (0/8)
    const int brf = (lane & 7) + ((lane >> 3) & 1) * 8; // B k row within k16
    const int bnf = (lane >> 4) << 3;                   // B n offset (0/8)

    issue(0, 0);
    cp_wait0();
    __syncthreads();

    const int nStages = kTotal >> 5;
    int buf = 0;
    for (int s = 0; s < nStages; s++) {
        if (s + 1 < nStages) issue(buf ^ 1, (s + 1) * 32);

        const int bufA = buf * 5120;
        const int bufB = buf * 4352;
#pragma unroll
        for (int kk = 0; kk < 2; kk++) {
            const int kc = kk * 16;
            uint32_t ah[2][4], al[2][4];
#pragma unroll
            for (int mi = 0; mi < 2; mi++) {
                int r = mw + mi * 16 + arf;
                ldsm4(ah[mi], smem_u32(sAh + bufA + r * 40 + kc + acf));
                ldsm4(al[mi], smem_u32(sAl + bufA + r * 40 + kc + acf));
            }
#pragma unroll
            for (int ng = 0; ng < 4; ng++) {
                int kr = kc + brf;
                int nc = nw + ng * 16 + bnf;
                uint32_t bh[4], bl[4];
                ldsm4t(bh, smem_u32(sBh + bufB + kr * 136 + nc));
                ldsm4t(bl, smem_u32(sBl + bufB + kr * 136 + nc));
#pragma unroll
                for (int mi = 0; mi < 2; mi++) {
#pragma unroll
                    for (int nj = 0; nj < 2; nj++) {
                        mma16816(acc[mi][ng * 2 + nj], ah[mi], bh[nj * 2], bh[nj * 2 + 1]);
                        mma16816(acc[mi][ng * 2 + nj], ah[mi], bl[nj * 2], bl[nj * 2 + 1]);
                        mma16816(acc[mi][ng * 2 + nj], al[mi], bh[nj * 2], bh[nj * 2 + 1]);
                    }
                }
            }
        }

        cp_wait0();
        __syncthreads();
        buf ^= 1;
    }

    // epilogue
#pragma unroll
    for (int mi = 0; mi < 2; mi++) {
#pragma unroll
        for (int ni = 0; ni < 8; ni++) {
            int row = m0 + mw + mi * 16 + (lane >> 2);
            int col = ncBase + nw + ni * 8 + (lane & 3) * 2;
            float2 c01 = {acc[mi][ni][0], acc[mi][ni][1]};
            float2 c23 = {acc[mi][ni][2], acc[mi][ni][3]};
            *(float2*)&C[(size_t)row * ldc + col]       = c01;
            *(float2*)&C[(size_t)(row + 8) * ldc + col] = c23;
        }
    }
}

// QKV: grid (24, 16). Column tiles: [0,2048)=q, [2048,2560)=k, [2560,3072)=v
__global__ void __launch_bounds__(256) qkv_gemm_tc() {
    const int n0 = blockIdx.x * 128;
    float* C;
    int ldc, ncb;
    if (n0 < 2048)      { C = g_q; ldc = 2048; ncb = n0;        }
    else if (n0 < 2560) { C = g_k; ldc = 512;  ncb = n0 - 2048; }
    else                { C = g_v; ldc = 512;  ncb = n0 - 2560; }
    gemm_core(g_Ah, g_Al, 4096, g_Bh, g_Bl, 3072, n0, C, ldc, ncb, 4096);
}

// out = g_o @ Wo : grid (16, 16)
__global__ void __launch_bounds__(256) out_gemm_tc(float* __restrict__ out) {
    const int n0 = blockIdx.x * 128;
    gemm_core(g_Oh, g_Ol, 2048, g_Wh, g_Wl, 2048, n0, out, 2048, n0, 2048);
}

// ============================================================================
// RoPE tables (double precision, tiny)
// ============================================================================
__global__ void rope_table_kernel(const int* __restrict__ positions)
{
    int idx = blockIdx.x * blockDim.x + threadIdx.x;   // t*32 + i
    if (idx >= T_TOK * 32) return;
    int t = idx >> 5;
    int i = idx & 31;
    double invf = pow(10000.0, -(double)i / 32.0);
    double fd   = (double)positions[t] * invf;
    g_cos[idx] = (float)cos(fd);
    g_sin[idx] = (float)sin(fd);
}

// ============================================================================
// Fused RMSNorm + RoPE (one warp per (token, head))
// ============================================================================
__global__ void norm_rope_kernel(const float* __restrict__ qw,
                                 const float* __restrict__ kw)
{
    int warpId = blockIdx.x * (blockDim.x >> 5) + (threadIdx.x >> 5);
    int lane   = threadIdx.x & 31;
    if (warpId >= T_TOK * (NH + NKV)) return;
    int t  = warpId / (NH + NKV);
    int hh = warpId % (NH + NKV);

    float* buf;
    int ld, col;
    const float* w;
    if (hh < NH) { buf = g_q; ld = NH * HD;  col = hh * HD;        w = qw; }
    else         { buf = g_k; ld = NKV * HD; col = (hh - NH) * HD; w = kw; }

    float x0 = buf[(size_t)t * ld + col + lane];
    float x1 = buf[(size_t)t * ld + col + 32 + lane];
    float ss = x0 * x0 + x1 * x1;
#pragma unroll
    for (int o = 16; o > 0; o >>= 1) ss += __shfl_xor_sync(0xffffffff, ss, o);
    float inv = rsqrtf(ss * (1.0f / 64.0f) + EPSV);
    x0 *= inv * w[lane];
    x1 *= inv * w[lane + 32];

    float c = g_cos[t * 32 + lane];
    float s = g_sin[t * 32 + lane];
    buf[(size_t)t * ld + col + lane]      = x0 * c - x1 * s;
    buf[(size_t)t * ld + col + 32 + lane] = x1 * c + x0 * s;
}

// ============================================================================
// Causal flash attention (unchanged — known good)
// ============================================================================
#define PLD 68
#define FLASH_SMEM (4 * 64 * PLD * (int)sizeof(float))

__global__ void __launch_bounds__(256) flash_kernel()
{
    extern __shared__ float sm[];
    float* Qt = sm;
    float* Kt = sm + 64 * PLD;
    float* Vs = sm + 2 * 64 * PLD;
    float* Pt = sm + 3 * 64 * PLD;

    const int qt  = blockIdx.x;
    const int h   = blockIdx.y;
    const int kvh = h >> 2;
    const int t   = threadIdx.x;
    const int tx  = t & 15;
    const int ty  = t >> 4;
    const int q0  = qt * 64;

#pragma unroll
    for (int u = 0; u < 4; u++) {
        int idx = u * 256 + t;
        int r = idx >> 4, cq = (idx & 15) * 4;
        float4 q4 = *(const float4*)&g_q[(size_t)(q0 + r) * (NH * HD) + h * HD + cq];
        Qt[(cq + 0) * PLD + r] = q4.x;
        Qt[(cq + 1) * PLD + r] = q4.y;
        Qt[(cq + 2) * PLD + r] = q4.z;
        Qt[(cq + 3) * PLD + r] = q4.w;
    }

    float acc[4][4];
    float m[4], l[4];
#pragma unroll
    for (int i = 0; i < 4; i++) {
        m[i] = -1e30f; l[i] = 0.0f;
#pragma unroll
        for (int j = 0; j < 4; j++) acc[i][j] = 0.0f;
    }

    __syncthreads();

    for (int kt = 0; kt <= qt; kt++) {
#pragma unroll
        for (int u = 0; u < 4; u++) {
            int idx = u * 256 + t;
            int r = idx >> 4, cq = (idx & 15) * 4;
            size_t gi = (size_t)(kt * 64 + r) * (NKV * HD) + kvh * HD + cq;
            float4 k4 = *(const float4*)&g_k[gi];
            float4 v4 = *(const float4*)&g_v[gi];
            Kt[(cq + 0) * PLD + r] = k4.x;
            Kt[(cq + 1) * PLD + r] = k4.y;
            Kt[(cq + 2) * PLD + r] = k4.z;
            Kt[(cq + 3) * PLD + r] = k4.w;
            *(float4*)&Vs[r * PLD + cq] = v4;
        }
        __syncthreads();

        float s[4][4];
#pragma unroll
        for (int i = 0; i < 4; i++)
#pragma unroll
            for (int j = 0; j < 4; j++) s[i][j] = 0.0f;

#pragma unroll 8
        for (int d = 0; d < 64; d++) {
            float4 av = *(const float4*)&Qt[d * PLD + ty * 4];
            float4 bv = *(const float4*)&Kt[d * PLD + tx * 4];
            float a[4] = {av.x, av.y, av.z, av.w};
            float b[4] = {bv.x, bv.y, bv.z, bv.w};
#pragma unroll
            for (int i = 0; i < 4; i++)
#pragma unroll
                for (int j = 0; j < 4; j++)
                    s[i][j] = fmaf(a[i], b[j], s[i][j]);
        }

        const bool diag = (kt == qt);
#pragma unroll
        for (int i = 0; i < 4; i++)
#pragma unroll
            for (int j = 0; j < 4; j++) {
                float v = s[i][j] * SM_SCALE;
                if (diag && (tx * 4 + j) > (ty * 4 + i)) v = -1e30f;
                s[i][j] = v;
            }

#pragma unroll
        for (int i = 0; i < 4; i++) {
            float rmax = fmaxf(fmaxf(s[i][0], s[i][1]), fmaxf(s[i][2], s[i][3]));
#pragma unroll
            for (int o = 8; o > 0; o >>= 1)
                rmax = fmaxf(rmax, __shfl_xor_sync(0xffffffff, rmax, o));
            float mnew  = fmaxf(m[i], rmax);
            float alpha = __expf(m[i] - mnew);
            m[i] = mnew;
            float rsum = 0.0f;
#pragma unroll
            for (int j = 0; j < 4; j++) {
                float p = __expf(s[i][j] - mnew);
                s[i][j] = p;
                rsum += p;
            }
#pragma unroll
            for (int o = 8; o > 0; o >>= 1)
                rsum += __shfl_xor_sync(0xffffffff, rsum, o);
            l[i] = l[i] * alpha + rsum;
#pragma unroll
            for (int j = 0; j < 4; j++) acc[i][j] *= alpha;
        }

#pragma unroll
        for (int j = 0; j < 4; j++) {
            float4 pc = {s[0][j], s[1][j], s[2][j], s[3][j]};
            *(float4*)&Pt[(tx * 4 + j) * PLD + ty * 4] = pc;
        }
        __syncthreads();

#pragma unroll 8
        for (int kk = 0; kk < 64; kk++) {
            float4 pv = *(const float4*)&Pt[kk * PLD + ty * 4];
            float4 vv = *(const float4*)&Vs[kk * PLD + tx * 4];
            float p[4] = {pv.x, pv.y, pv.z, pv.w};
            float v[4] = {vv.x, vv.y, vv.z, vv.w};
#pragma unroll
            for (int i = 0; i < 4; i++)
#pragma unroll
                for (int j = 0; j < 4; j++)
                    acc[i][j] = fmaf(p[i], v[j], acc[i][j]);
        }
        __syncthreads();
    }

#pragma unroll
    for (int i = 0; i < 4; i++) {
        float inv = 1.0f / l[i];
        float4 c = {acc[i][0] * inv, acc[i][1] * inv, acc[i][2] * inv, acc[i][3] * inv};
        *(float4*)&g_o[(size_t)(q0 + ty * 4 + i) * (NH * HD) + h * HD + tx * 4] = c;
    }
}

// ============================================================================
// launch
// ============================================================================
extern "C" void kernel_launch(void* const* d_in, const int* in_sizes, int n_in,
                              void* d_out, int out_size)
{
    const float* hidden = (const float*)d_in[0];
    const float* mu     = (const float*)d_in[1];
    const float* Wq     = (const float*)d_in[2];
    const float* Wk     = (const float*)d_in[3];
    const float* Wv     = (const float*)d_in[4];
    const float* Wo     = (const float*)d_in[5];
    const float* Wmq    = (const float*)d_in[6];
    const float* Wmk    = (const float*)d_in[7];
    const float* Wmv    = (const float*)d_in[8];
    const float* qnw    = (const float*)d_in[9];
    const float* knw    = (const float*)d_in[10];
    const int*   pos    = (const int*)d_in[11];
    float* out          = (float*)d_out;

    cudaFuncSetAttribute(flash_kernel, cudaFuncAttributeMaxDynamicSharedMemorySize, FLASH_SMEM);
    cudaFuncSetAttribute(qkv_gemm_tc, cudaFuncAttributeMaxDynamicSharedMemorySize, SMEM_GEMM_BYTES);
    cudaFuncSetAttribute(out_gemm_tc, cudaFuncAttributeMaxDynamicSharedMemorySize, SMEM_GEMM_BYTES);

    // bf16 split conversions
    convert_A_kernel<<<(T_TOK * 1024 + 255) / 256, 256>>>(hidden, mu);
    convert_B_kernel<<<(4096 * 768 + 255) / 256, 256>>>(Wq, Wk, Wv, Wmq, Wmk, Wmv);
    convert_Wo_kernel<<<(2048 * 512 + 255) / 256, 256>>>(Wo);

    // QKV projection on tensor cores
    qkv_gemm_tc<<<dim3(24, 16), 256, SMEM_GEMM_BYTES>>>();

    // RoPE tables + RMSNorm/RoPE
    rope_table_kernel<<<(T_TOK * 32 + 255) / 256, 256>>>(pos);
    norm_rope_kernel<<<(T_TOK * (NH + NKV) + 7) / 8, 256>>>(qnw, knw);

    // causal flash attention
    flash_kernel<<<dim3(T_TOK / 64, NH), 256, FLASH_SMEM>>>();

    // output projection on tensor cores
    convert_O_kernel<<<(2048 * 512 + 255) / 256, 256>>>();
    out_gemm_tc<<<dim3(16, 16), 256, SMEM_GEMM_BYTES>>>(out);
}

// round 6
// speedup vs baseline: 2.9697x; 1.0267x over previous
#include <cuda_runtime.h>
#include <cuda_bf16.h>
#include <math.h>
#include <stdint.h>

// ---------------- problem constants ----------------
#define T_TOK 2048
#define HID   2048
#define NH    32
#define NKV   8
#define HD    64
#define EPSV  1e-6f
#define SM_SCALE 0.125f

// ---------------- fp32 scratch ----------------
__device__ float g_q[T_TOK * NH * HD];     // [2048, 2048]
__device__ float g_k[T_TOK * NKV * HD];    // [2048, 512]
__device__ float g_v[T_TOK * NKV * HD];    // [2048, 512]
__device__ float g_o[T_TOK * NH * HD];     // [2048, 2048]
__device__ float g_cos[T_TOK * (HD / 2)];
__device__ float g_sin[T_TOK * (HD / 2)];

// ---------------- bf16 split scratch ----------------
__device__ __nv_bfloat16 g_Ah[T_TOK * 4096];   // [2048,4096] = [hidden|mu] hi
__device__ __nv_bfloat16 g_Al[T_TOK * 4096];   // lo
__device__ __nv_bfloat16 g_Bh[4096 * 3072];    // [[Wq|Wk|Wv];[Wmq|Wmk|Wmv]] hi
__device__ __nv_bfloat16 g_Bl[4096 * 3072];
__device__ __nv_bfloat16 g_Oh[T_TOK * 2048];   // g_o hi/lo
__device__ __nv_bfloat16 g_Ol[T_TOK * 2048];
__device__ __nv_bfloat16 g_Wh[2048 * 2048];    // Wo hi/lo
__device__ __nv_bfloat16 g_Wl[2048 * 2048];

// ============================================================================
// PTX helpers
// ============================================================================
__device__ __forceinline__ uint32_t smem_u32(const void* p) {
    return (uint32_t)__cvta_generic_to_shared(p);
}
__device__ __forceinline__ void ldsm4(uint32_t (&r)[4], uint32_t addr) {
    asm volatile("ldmatrix.sync.aligned.m8n8.x4.shared.b16 {%0,%1,%2,%3}, [%4];"
                 : "=r"(r[0]), "=r"(r[1]), "=r"(r[2]), "=r"(r[3]) : "r"(addr));
}
__device__ __forceinline__ void ldsm4t(uint32_t (&r)[4], uint32_t addr) {
    asm volatile("ldmatrix.sync.aligned.m8n8.x4.trans.shared.b16 {%0,%1,%2,%3}, [%4];"
                 : "=r"(r[0]), "=r"(r[1]), "=r"(r[2]), "=r"(r[3]) : "r"(addr));
}
__device__ __forceinline__ void mma16816(float (&c)[4], const uint32_t (&a)[4],
                                         uint32_t b0, uint32_t b1) {
    asm volatile("mma.sync.aligned.m16n8k16.row.col.f32.bf16.bf16.f32 "
                 "{%0,%1,%2,%3}, {%4,%5,%6,%7}, {%8,%9}, {%0,%1,%2,%3};"
                 : "+f"(c[0]), "+f"(c[1]), "+f"(c[2]), "+f"(c[3])
                 : "r"(a[0]), "r"(a[1]), "r"(a[2]), "r"(a[3]), "r"(b0), "r"(b1));
}
__device__ __forceinline__ void cpasync16(uint32_t dst, const void* src) {
    asm volatile("cp.async.cg.shared.global [%0], [%1], 16;" :: "r"(dst), "l"(src));
}
__device__ __forceinline__ void cp_commit() {
    asm volatile("cp.async.commit_group;" ::: "memory");
}
__device__ __forceinline__ void cp_wait0() {
    asm volatile("cp.async.wait_group 0;" ::: "memory");
}

// ============================================================================
// bf16 split conversion kernels (x = hi + lo)
// ============================================================================
__device__ __forceinline__ uint32_t packh(__nv_bfloat16 a, __nv_bfloat16 b) {
    __nv_bfloat162 v = __halves2bfloat162(a, b);
    return *reinterpret_cast<uint32_t*>(&v);
}
__device__ __forceinline__ void split_store4(__nv_bfloat16* dh, __nv_bfloat16* dl,
                                             size_t off, float4 x) {
    __nv_bfloat16 h0 = __float2bfloat16(x.x);
    __nv_bfloat16 h1 = __float2bfloat16(x.y);
    __nv_bfloat16 h2 = __float2bfloat16(x.z);
    __nv_bfloat16 h3 = __float2bfloat16(x.w);
    __nv_bfloat16 l0 = __float2bfloat16(x.x - __bfloat162float(h0));
    __nv_bfloat16 l1 = __float2bfloat16(x.y - __bfloat162float(h1));
    __nv_bfloat16 l2 = __float2bfloat16(x.z - __bfloat162float(h2));
    __nv_bfloat16 l3 = __float2bfloat16(x.w - __bfloat162float(h3));
    uint2 hv = {packh(h0, h1), packh(h2, h3)};
    uint2 lv = {packh(l0, l1), packh(l2, l3)};
    *reinterpret_cast<uint2*>(dh + off) = hv;
    *reinterpret_cast<uint2*>(dl + off) = lv;
}

// A = [hidden | mu] : [2048, 4096]
__global__ void convert_A_kernel(const float* __restrict__ hidden,
                                 const float* __restrict__ mu) {
    int idx = blockIdx.x * blockDim.x + threadIdx.x;   // per float4
    if (idx >= T_TOK * 1024) return;
    int t = idx >> 10, c4 = idx & 1023;
    float4 x = (c4 < 512) ? ((const float4*)hidden)[t * 512 + c4]
                          : ((const float4*)mu)[t * 512 + c4 - 512];
    split_store4(g_Ah, g_Al, (size_t)t * 4096 + c4 * 4, x);
}

// B : [4096, 3072]; rows 0-2047 = [Wq|Wk|Wv], rows 2048+ = [Wmq|Wmk|Wmv]
__global__ void convert_B_kernel(const float* __restrict__ Wq, const float* __restrict__ Wk,
                                 const float* __restrict__ Wv, const float* __restrict__ Wmq,
                                 const float* __restrict__ Wmk, const float* __restrict__ Wmv) {
    int idx = blockIdx.x * blockDim.x + threadIdx.x;   // per float4
    if (idx >= 4096 * 768) return;
    int k = idx / 768, c4 = idx % 768;
    int n = c4 * 4;
    int kk = k & 2047;
    const float* src;
    size_t off;
    if (n < 2048)      { src = (k < 2048) ? Wq : Wmq; off = (size_t)kk * 2048 + n; }
    else if (n < 2560) { src = (k < 2048) ? Wk : Wmk; off = (size_t)kk * 512 + (n - 2048); }
    else               { src = (k < 2048) ? Wv : Wmv; off = (size_t)kk * 512 + (n - 2560); }
    float4 x = *(const float4*)&src[off];
    split_store4(g_Bh, g_Bl, (size_t)k * 3072 + n, x);
}

__global__ void convert_Wo_kernel(const float* __restrict__ Wo) {
    int idx = blockIdx.x * blockDim.x + threadIdx.x;
    if (idx >= 2048 * 512) return;
    float4 x = ((const float4*)Wo)[idx];
    split_store4(g_Wh, g_Wl, (size_t)idx * 4, x);
}

__global__ void convert_O_kernel() {
    int idx = blockIdx.x * blockDim.x + threadIdx.x;
    if (idx >= 2048 * 512) return;
    float4 x = ((const float4*)g_o)[idx];
    split_store4(g_Oh, g_Ol, (size_t)idx * 4, x);
}

// ============================================================================
// Tensor-core GEMM, 3-term bf16 split. Block 128x128, 8 warps, warp 32x64.
// smem (bf16 units): A pad-stride 40, B pad-stride 136 (conflict-free ldmatrix).
// ============================================================================
#define SM_AH 0
#define SM_AL 10240        // 2*128*40
#define SM_BH 20480
#define SM_BL 29184        // +2*32*136
#define SMEM_GEMM_BYTES (37888 * 2)

__device__ __forceinline__ void gemm_core(
    const __nv_bfloat16* __restrict__ Ah, const __nv_bfloat16* __restrict__ Al, int lda,
    const __nv_bfloat16* __restrict__ Bh, const __nv_bfloat16* __restrict__ Bl, int ldb, int nb,
    float* __restrict__ C, int ldc, int ncBase, int kTotal)
{
    extern __shared__ __nv_bfloat16 smem[];
    __nv_bfloat16* sAh = smem + SM_AH;
    __nv_bfloat16* sAl = smem + SM_AL;
    __nv_bfloat16* sBh = smem + SM_BH;
    __nv_bfloat16* sBl = smem + SM_BL;

    const int t    = threadIdx.x;
    const int lane = t & 31;
    const int warp = t >> 5;
    const int mw   = (warp >> 1) * 32;   // warp m offset in tile
    const int nw   = (warp & 1) * 64;    // warp n offset in tile
    const int m0   = blockIdx.y * 128;

    float acc[2][8][4];
#pragma unroll
    for (int i = 0; i < 2; i++)
#pragma unroll
        for (int j = 0; j < 8; j++)
#pragma unroll
            for (int q = 0; q < 4; q++) acc[i][j][q] = 0.0f;

    // async copy: 8-element (16B) chunks; A tile 128x32 = 512 chunks,
    // B tile 32x128 = 512 chunks; 256 threads x 2 iterations each.
    auto issue = [&](int buf, int k0) {
#pragma unroll
        for (int i = 0; i < 2; i++) {
            const int c  = t + i * 256;           // chunk id 0..511
            const int ra = c >> 2, ca = (c & 3) * 8;    // A: row, k-elem offset
            const size_t ga = (size_t)(m0 + ra) * lda + k0 + ca;
            cpasync16(smem_u32(sAh + buf * 5120 + ra * 40 + ca), Ah + ga);
            cpasync16(smem_u32(sAl + buf * 5120 + ra * 40 + ca), Al + ga);
            const int rb = c >> 4, cb = (c & 15) * 8;   // B: k row, n-elem offset
            const size_t gb = (size_t)(k0 + rb) * ldb + nb + cb;
            cpasync16(smem_u32(sBh + buf * 4352 + rb * 136 + cb), Bh + gb);
            cpasync16(smem_u32(sBl + buf * 4352 + rb * 136 + cb), Bl + gb);
        }
        cp_commit();
    };

    // ldmatrix lane mapping
    const int arf = lane & 15;                          // A row within m16
    const int acf = (lane >> 4) << 3;                   // A k offset (0/8)
    const int brf = (lane & 7) + ((lane >> 3) & 1) * 8; // B k row within k16
    const int bnf = (lane >> 4) << 3;                   // B n offset (0/8)

    issue(0, 0);
    cp_wait0();
    __syncthreads();

    const int nStages = kTotal >> 5;
    int buf = 0;
    for (int s = 0; s < nStages; s++) {
        if (s + 1 < nStages) issue(buf ^ 1, (s + 1) * 32);

        const int bufA = buf * 5120;
        const int bufB = buf * 4352;
#pragma unroll
        for (int kk = 0; kk < 2; kk++) {
            const int kc = kk * 16;
            uint32_t ah[2][4], al[2][4];
#pragma unroll
            for (int mi = 0; mi < 2; mi++) {
                int r = mw + mi * 16 + arf;
                ldsm4(ah[mi], smem_u32(sAh + bufA + r * 40 + kc + acf));
                ldsm4(al[mi], smem_u32(sAl + bufA + r * 40 + kc + acf));
            }
#pragma unroll
            for (int ng = 0; ng < 4; ng++) {
                int kr = kc + brf;
                int nc = nw + ng * 16 + bnf;
                uint32_t bh[4], bl[4];
                ldsm4t(bh, smem_u32(sBh + bufB + kr * 136 + nc));
                ldsm4t(bl, smem_u32(sBl + bufB + kr * 136 + nc));
#pragma unroll
                for (int mi = 0; mi < 2; mi++) {
#pragma unroll
                    for (int nj = 0; nj < 2; nj++) {
                        mma16816(acc[mi][ng * 2 + nj], ah[mi], bh[nj * 2], bh[nj * 2 + 1]);
                        mma16816(acc[mi][ng * 2 + nj], ah[mi], bl[nj * 2], bl[nj * 2 + 1]);
                        mma16816(acc[mi][ng * 2 + nj], al[mi], bh[nj * 2], bh[nj * 2 + 1]);
                    }
                }
            }
        }

        cp_wait0();
        __syncthreads();
        buf ^= 1;
    }

    // epilogue
#pragma unroll
    for (int mi = 0; mi < 2; mi++) {
#pragma unroll
        for (int ni = 0; ni < 8; ni++) {
            int row = m0 + mw + mi * 16 + (lane >> 2);
            int col = ncBase + nw + ni * 8 + (lane & 3) * 2;
            float2 c01 = {acc[mi][ni][0], acc[mi][ni][1]};
            float2 c23 = {acc[mi][ni][2], acc[mi][ni][3]};
            *(float2*)&C[(size_t)row * ldc + col]       = c01;
            *(float2*)&C[(size_t)(row + 8) * ldc + col] = c23;
        }
    }
}

// QKV: grid (24, 16). Column tiles: [0,2048)=q, [2048,2560)=k, [2560,3072)=v
__global__ void __launch_bounds__(256) qkv_gemm_tc() {
    const int n0 = blockIdx.x * 128;
    float* C;
    int ldc, ncb;
    if (n0 < 2048)      { C = g_q; ldc = 2048; ncb = n0;        }
    else if (n0 < 2560) { C = g_k; ldc = 512;  ncb = n0 - 2048; }
    else                { C = g_v; ldc = 512;  ncb = n0 - 2560; }
    gemm_core(g_Ah, g_Al, 4096, g_Bh, g_Bl, 3072, n0, C, ldc, ncb, 4096);
}

// out = g_o @ Wo : grid (16, 16)
__global__ void __launch_bounds__(256) out_gemm_tc(float* __restrict__ out) {
    const int n0 = blockIdx.x * 128;
    gemm_core(g_Oh, g_Ol, 2048, g_Wh, g_Wl, 2048, n0, out, 2048, n0, 2048);
}

// ============================================================================
// RoPE tables (double precision, tiny)
// ============================================================================
__global__ void rope_table_kernel(const int* __restrict__ positions)
{
    int idx = blockIdx.x * blockDim.x + threadIdx.x;   // t*32 + i
    if (idx >= T_TOK * 32) return;
    int t = idx >> 5;
    int i = idx & 31;
    double invf = pow(10000.0, -(double)i / 32.0);
    double fd   = (double)positions[t] * invf;
    g_cos[idx] = (float)cos(fd);
    g_sin[idx] = (float)sin(fd);
}

// ============================================================================
// Fused RMSNorm + RoPE (one warp per (token, head))
// ============================================================================
__global__ void norm_rope_kernel(const float* __restrict__ qw,
                                 const float* __restrict__ kw)
{
    int warpId = blockIdx.x * (blockDim.x >> 5) + (threadIdx.x >> 5);
    int lane   = threadIdx.x & 31;
    if (warpId >= T_TOK * (NH + NKV)) return;
    int t  = warpId / (NH + NKV);
    int hh = warpId % (NH + NKV);

    float* buf;
    int ld, col;
    const float* w;
    if (hh < NH) { buf = g_q; ld = NH * HD;  col = hh * HD;        w = qw; }
    else         { buf = g_k; ld = NKV * HD; col = (hh - NH) * HD; w = kw; }

    float x0 = buf[(size_t)t * ld + col + lane];
    float x1 = buf[(size_t)t * ld + col + 32 + lane];
    float ss = x0 * x0 + x1 * x1;
#pragma unroll
    for (int o = 16; o > 0; o >>= 1) ss += __shfl_xor_sync(0xffffffff, ss, o);
    float inv = rsqrtf(ss * (1.0f / 64.0f) + EPSV);
    x0 *= inv * w[lane];
    x1 *= inv * w[lane + 32];

    float c = g_cos[t * 32 + lane];
    float s = g_sin[t * 32 + lane];
    buf[(size_t)t * ld + col + lane]      = x0 * c - x1 * s;
    buf[(size_t)t * ld + col + 32 + lane] = x1 * c + x0 * s;
}

// ============================================================================
// Causal flash attention (unchanged — known good)
// ============================================================================
#define PLD 68
#define FLASH_SMEM (4 * 64 * PLD * (int)sizeof(float))

__global__ void __launch_bounds__(256) flash_kernel()
{
    extern __shared__ float sm[];
    float* Qt = sm;
    float* Kt = sm + 64 * PLD;
    float* Vs = sm + 2 * 64 * PLD;
    float* Pt = sm + 3 * 64 * PLD;

    const int qt  = blockIdx.x;
    const int h   = blockIdx.y;
    const int kvh = h >> 2;
    const int t   = threadIdx.x;
    const int tx  = t & 15;
    const int ty  = t >> 4;
    const int q0  = qt * 64;

#pragma unroll
    for (int u = 0; u < 4; u++) {
        int idx = u * 256 + t;
        int r = idx >> 4, cq = (idx & 15) * 4;
        float4 q4 = *(const float4*)&g_q[(size_t)(q0 + r) * (NH * HD) + h * HD + cq];
        Qt[(cq + 0) * PLD + r] = q4.x;
        Qt[(cq + 1) * PLD + r] = q4.y;
        Qt[(cq + 2) * PLD + r] = q4.z;
        Qt[(cq + 3) * PLD + r] = q4.w;
    }

    float acc[4][4];
    float m[4], l[4];
#pragma unroll
    for (int i = 0; i < 4; i++) {
        m[i] = -1e30f; l[i] = 0.0f;
#pragma unroll
        for (int j = 0; j < 4; j++) acc[i][j] = 0.0f;
    }

    __syncthreads();

    for (int kt = 0; kt <= qt; kt++) {
#pragma unroll
        for (int u = 0; u < 4; u++) {
            int idx = u * 256 + t;
            int r = idx >> 4, cq = (idx & 15) * 4;
            size_t gi = (size_t)(kt * 64 + r) * (NKV * HD) + kvh * HD + cq;
            float4 k4 = *(const float4*)&g_k[gi];
            float4 v4 = *(const float4*)&g_v[gi];
            Kt[(cq + 0) * PLD + r] = k4.x;
            Kt[(cq + 1) * PLD + r] = k4.y;
            Kt[(cq + 2) * PLD + r] = k4.z;
            Kt[(cq + 3) * PLD + r] = k4.w;
            *(float4*)&Vs[r * PLD + cq] = v4;
        }
        __syncthreads();

        float s[4][4];
#pragma unroll
        for (int i = 0; i < 4; i++)
#pragma unroll
            for (int j = 0; j < 4; j++) s[i][j] = 0.0f;

#pragma unroll 8
        for (int d = 0; d < 64; d++) {
            float4 av = *(const float4*)&Qt[d * PLD + ty * 4];
            float4 bv = *(const float4*)&Kt[d * PLD + tx * 4];
            float a[4] = {av.x, av.y, av.z, av.w};
            float b[4] = {bv.x, bv.y, bv.z, bv.w};
#pragma unroll
            for (int i = 0; i < 4; i++)
#pragma unroll
                for (int j = 0; j < 4; j++)
                    s[i][j] = fmaf(a[i], b[j], s[i][j]);
        }

        const bool diag = (kt == qt);
#pragma unroll
        for (int i = 0; i < 4; i++)
#pragma unroll
            for (int j = 0; j < 4; j++) {
                float v = s[i][j] * SM_SCALE;
                if (diag && (tx * 4 + j) > (ty * 4 + i)) v = -1e30f;
                s[i][j] = v;
            }

#pragma unroll
        for (int i = 0; i < 4; i++) {
            float rmax = fmaxf(fmaxf(s[i][0], s[i][1]), fmaxf(s[i][2], s[i][3]));
#pragma unroll
            for (int o = 8; o > 0; o >>= 1)
                rmax = fmaxf(rmax, __shfl_xor_sync(0xffffffff, rmax, o));
            float mnew  = fmaxf(m[i], rmax);
            float alpha = __expf(m[i] - mnew);
            m[i] = mnew;
            float rsum = 0.0f;
#pragma unroll
            for (int j = 0; j < 4; j++) {
                float p = __expf(s[i][j] - mnew);
                s[i][j] = p;
                rsum += p;
            }
#pragma unroll
            for (int o = 8; o > 0; o >>= 1)
                rsum += __shfl_xor_sync(0xffffffff, rsum, o);
            l[i] = l[i] * alpha + rsum;
#pragma unroll
            for (int j = 0; j < 4; j++) acc[i][j] *= alpha;
        }

#pragma unroll
        for (int j = 0; j < 4; j++) {
            float4 pc = {s[0][j], s[1][j], s[2][j], s[3][j]};
            *(float4*)&Pt[(tx * 4 + j) * PLD + ty * 4] = pc;
        }
        __syncthreads();

#pragma unroll 8
        for (int kk = 0; kk < 64; kk++) {
            float4 pv = *(const float4*)&Pt[kk * PLD + ty * 4];
            float4 vv = *(const float4*)&Vs[kk * PLD + tx * 4];
            float p[4] = {pv.x, pv.y, pv.z, pv.w};
            float v[4] = {vv.x, vv.y, vv.z, vv.w};
#pragma unroll
            for (int i = 0; i < 4; i++)
#pragma unroll
                for (int j = 0; j < 4; j++)
                    acc[i][j] = fmaf(p[i], v[j], acc[i][j]);
        }
        __syncthreads();
    }

#pragma unroll
    for (int i = 0; i < 4; i++) {
        float inv = 1.0f / l[i];
        float4 c = {acc[i][0] * inv, acc[i][1] * inv, acc[i][2] * inv, acc[i][3] * inv};
        *(float4*)&g_o[(size_t)(q0 + ty * 4 + i) * (NH * HD) + h * HD + tx * 4] = c;
    }
}

// ============================================================================
// launch
// ============================================================================
extern "C" void kernel_launch(void* const* d_in, const int* in_sizes, int n_in,
                              void* d_out, int out_size)
{
    const float* hidden = (const float*)d_in[0];
    const float* mu     = (const float*)d_in[1];
    const float* Wq     = (const float*)d_in[2];
    const float* Wk     = (const float*)d_in[3];
    const float* Wv     = (const float*)d_in[4];
    const float* Wo     = (const float*)d_in[5];
    const float* Wmq    = (const float*)d_in[6];
    const float* Wmk    = (const float*)d_in[7];
    const float* Wmv    = (const float*)d_in[8];
    const float* qnw    = (const float*)d_in[9];
    const float* knw    = (const float*)d_in[10];
    const int*   pos    = (const int*)d_in[11];
    float* out          = (float*)d_out;

    cudaFuncSetAttribute(flash_kernel, cudaFuncAttributeMaxDynamicSharedMemorySize, FLASH_SMEM);
    cudaFuncSetAttribute(qkv_gemm_tc, cudaFuncAttributeMaxDynamicSharedMemorySize, SMEM_GEMM_BYTES);
    cudaFuncSetAttribute(out_gemm_tc, cudaFuncAttributeMaxDynamicSharedMemorySize, SMEM_GEMM_BYTES);

    // bf16 split conversions
    convert_A_kernel<<<(T_TOK * 1024 + 255) / 256, 256>>>(hidden, mu);
    convert_B_kernel<<<(4096 * 768 + 255) / 256, 256>>>(Wq, Wk, Wv, Wmq, Wmk, Wmv);
    convert_Wo_kernel<<<(2048 * 512 + 255) / 256, 256>>>(Wo);

    // QKV projection on tensor cores
    qkv_gemm_tc<<<dim3(24, 16), 256, SMEM_GEMM_BYTES>>>();

    // RoPE tables + RMSNorm/RoPE
    rope_table_kernel<<<(T_TOK * 32 + 255) / 256, 256>>>(pos);
    norm_rope_kernel<<<(T_TOK * (NH + NKV) + 7) / 8, 256>>>(qnw, knw);

    // causal flash attention
    flash_kernel<<<dim3(T_TOK / 64, NH), 256, FLASH_SMEM>>>();

    // output projection on tensor cores
    convert_O_kernel<<<(2048 * 512 + 255) / 256, 256>>>();
    out_gemm_tc<<<dim3(16, 16), 256, SMEM_GEMM_BYTES>>>(out);
}

// round 7
// speedup vs baseline: 2.9869x; 1.0058x over previous
#include <cuda_runtime.h>
#include <cuda_bf16.h>
#include <math.h>
#include <stdint.h>

// ---------------- problem constants ----------------
#define T_TOK 2048
#define HID   2048
#define NH    32
#define NKV   8
#define HD    64
#define EPSV  1e-6f
#define SM_SCALE 0.125f

// ---------------- fp32 scratch ----------------
__device__ float g_q[T_TOK * NH * HD];     // [2048, 2048]
__device__ float g_k[T_TOK * NKV * HD];    // [2048, 512]
__device__ float g_v[T_TOK * NKV * HD];    // [2048, 512]
__device__ float g_o[T_TOK * NH * HD];     // [2048, 2048]
__device__ float g_cos[T_TOK * (HD / 2)];
__device__ float g_sin[T_TOK * (HD / 2)];

// ---------------- bf16 split scratch ----------------
__device__ __nv_bfloat16 g_Ah[T_TOK * 4096];   // [2048,4096] = [hidden|mu] hi
__device__ __nv_bfloat16 g_Al[T_TOK * 4096];   // lo
__device__ __nv_bfloat16 g_Bh[4096 * 3072];    // [[Wq|Wk|Wv];[Wmq|Wmk|Wmv]] hi
__device__ __nv_bfloat16 g_Bl[4096 * 3072];
__device__ __nv_bfloat16 g_Oh[T_TOK * 2048];   // g_o hi/lo
__device__ __nv_bfloat16 g_Ol[T_TOK * 2048];
__device__ __nv_bfloat16 g_Wh[2048 * 2048];    // Wo hi/lo
__device__ __nv_bfloat16 g_Wl[2048 * 2048];

// ============================================================================
// PTX helpers
// ============================================================================
__device__ __forceinline__ uint32_t smem_u32(const void* p) {
    return (uint32_t)__cvta_generic_to_shared(p);
}
__device__ __forceinline__ void ldsm4(uint32_t (&r)[4], uint32_t addr) {
    asm volatile("ldmatrix.sync.aligned.m8n8.x4.shared.b16 {%0,%1,%2,%3}, [%4];"
                 : "=r"(r[0]), "=r"(r[1]), "=r"(r[2]), "=r"(r[3]) : "r"(addr));
}
__device__ __forceinline__ void ldsm4t(uint32_t (&r)[4], uint32_t addr) {
    asm volatile("ldmatrix.sync.aligned.m8n8.x4.trans.shared.b16 {%0,%1,%2,%3}, [%4];"
                 : "=r"(r[0]), "=r"(r[1]), "=r"(r[2]), "=r"(r[3]) : "r"(addr));
}
__device__ __forceinline__ void mma16816(float (&c)[4], const uint32_t (&a)[4],
                                         uint32_t b0, uint32_t b1) {
    asm volatile("mma.sync.aligned.m16n8k16.row.col.f32.bf16.bf16.f32 "
                 "{%0,%1,%2,%3}, {%4,%5,%6,%7}, {%8,%9}, {%0,%1,%2,%3};"
                 : "+f"(c[0]), "+f"(c[1]), "+f"(c[2]), "+f"(c[3])
                 : "r"(a[0]), "r"(a[1]), "r"(a[2]), "r"(a[3]), "r"(b0), "r"(b1));
}
__device__ __forceinline__ void cpasync16(uint32_t dst, const void* src) {
    asm volatile("cp.async.cg.shared.global [%0], [%1], 16;" :: "r"(dst), "l"(src));
}
__device__ __forceinline__ void cp_commit() {
    asm volatile("cp.async.commit_group;" ::: "memory");
}
__device__ __forceinline__ void cp_wait0() {
    asm volatile("cp.async.wait_group 0;" ::: "memory");
}

// ============================================================================
// bf16 split conversion kernels (x = hi + lo)
// ============================================================================
__device__ __forceinline__ uint32_t packh(__nv_bfloat16 a, __nv_bfloat16 b) {
    __nv_bfloat162 v = __halves2bfloat162(a, b);
    return *reinterpret_cast<uint32_t*>(&v);
}
__device__ __forceinline__ void split_store4(__nv_bfloat16* dh, __nv_bfloat16* dl,
                                             size_t off, float4 x) {
    __nv_bfloat16 h0 = __float2bfloat16(x.x);
    __nv_bfloat16 h1 = __float2bfloat16(x.y);
    __nv_bfloat16 h2 = __float2bfloat16(x.z);
    __nv_bfloat16 h3 = __float2bfloat16(x.w);
    __nv_bfloat16 l0 = __float2bfloat16(x.x - __bfloat162float(h0));
    __nv_bfloat16 l1 = __float2bfloat16(x.y - __bfloat162float(h1));
    __nv_bfloat16 l2 = __float2bfloat16(x.z - __bfloat162float(h2));
    __nv_bfloat16 l3 = __float2bfloat16(x.w - __bfloat162float(h3));
    uint2 hv = {packh(h0, h1), packh(h2, h3)};
    uint2 lv = {packh(l0, l1), packh(l2, l3)};
    *reinterpret_cast<uint2*>(dh + off) = hv;
    *reinterpret_cast<uint2*>(dl + off) = lv;
}

// A = [hidden | mu] : [2048, 4096]
__global__ void convert_A_kernel(const float* __restrict__ hidden,
                                 const float* __restrict__ mu) {
    int idx = blockIdx.x * blockDim.x + threadIdx.x;   // per float4
    if (idx >= T_TOK * 1024) return;
    int t = idx >> 10, c4 = idx & 1023;
    float4 x = (c4 < 512) ? ((const float4*)hidden)[t * 512 + c4]
                          : ((const float4*)mu)[t * 512 + c4 - 512];
    split_store4(g_Ah, g_Al, (size_t)t * 4096 + c4 * 4, x);
}

// B : [4096, 3072]; rows 0-2047 = [Wq|Wk|Wv], rows 2048+ = [Wmq|Wmk|Wmv]
__global__ void convert_B_kernel(const float* __restrict__ Wq, const float* __restrict__ Wk,
                                 const float* __restrict__ Wv, const float* __restrict__ Wmq,
                                 const float* __restrict__ Wmk, const float* __restrict__ Wmv) {
    int idx = blockIdx.x * blockDim.x + threadIdx.x;   // per float4
    if (idx >= 4096 * 768) return;
    int k = idx / 768, c4 = idx % 768;
    int n = c4 * 4;
    int kk = k & 2047;
    const float* src;
    size_t off;
    if (n < 2048)      { src = (k < 2048) ? Wq : Wmq; off = (size_t)kk * 2048 + n; }
    else if (n < 2560) { src = (k < 2048) ? Wk : Wmk; off = (size_t)kk * 512 + (n - 2048); }
    else               { src = (k < 2048) ? Wv : Wmv; off = (size_t)kk * 512 + (n - 2560); }
    float4 x = *(const float4*)&src[off];
    split_store4(g_Bh, g_Bl, (size_t)k * 3072 + n, x);
}

__global__ void convert_Wo_kernel(const float* __restrict__ Wo) {
    int idx = blockIdx.x * blockDim.x + threadIdx.x;
    if (idx >= 2048 * 512) return;
    float4 x = ((const float4*)Wo)[idx];
    split_store4(g_Wh, g_Wl, (size_t)idx * 4, x);
}

__global__ void convert_O_kernel() {
    int idx = blockIdx.x * blockDim.x + threadIdx.x;
    if (idx >= 2048 * 512) return;
    float4 x = ((const float4*)g_o)[idx];
    split_store4(g_Oh, g_Ol, (size_t)idx * 4, x);
}

// ============================================================================
// Tensor-core GEMM, 3-term bf16 split. Block 128x128, 8 warps, warp 32x64.
// smem (bf16 units): A pad-stride 40, B pad-stride 136 (conflict-free ldmatrix).
// ============================================================================
#define SM_AH 0
#define SM_AL 10240        // 2*128*40
#define SM_BH 20480
#define SM_BL 29184        // +2*32*136
#define SMEM_GEMM_BYTES (37888 * 2)

__device__ __forceinline__ void gemm_core(
    const __nv_bfloat16* __restrict__ Ah, const __nv_bfloat16* __restrict__ Al, int lda,
    const __nv_bfloat16* __restrict__ Bh, const __nv_bfloat16* __restrict__ Bl, int ldb, int nb,
    float* __restrict__ C, int ldc, int ncBase, int kTotal)
{
    extern __shared__ __nv_bfloat16 smem[];
    __nv_bfloat16* sAh = smem + SM_AH;
    __nv_bfloat16* sAl = smem + SM_AL;
    __nv_bfloat16* sBh = smem + SM_BH;
    __nv_bfloat16* sBl = smem + SM_BL;

    const int t    = threadIdx.x;
    const int lane = t & 31;
    const int warp = t >> 5;
    const int mw   = (warp >> 1) * 32;   // warp m offset in tile
    const int nw   = (warp & 1) * 64;    // warp n offset in tile
    const int m0   = blockIdx.y * 128;

    float acc[2][8][4];
#pragma unroll
    for (int i = 0; i < 2; i++)
#pragma unroll
        for (int j = 0; j < 8; j++)
#pragma unroll
            for (int q = 0; q < 4; q++) acc[i][j][q] = 0.0f;

    // async copy: 8-element (16B) chunks; A tile 128x32 = 512 chunks,
    // B tile 32x128 = 512 chunks; 256 threads x 2 iterations each.
    auto issue = [&](int buf, int k0) {
#pragma unroll
        for (int i = 0; i < 2; i++) {
            const int c  = t + i * 256;           // chunk id 0..511
            const int ra = c >> 2, ca = (c & 3) * 8;    // A: row, k-elem offset
            const size_t ga = (size_t)(m0 + ra) * lda + k0 + ca;
            cpasync16(smem_u32(sAh + buf * 5120 + ra * 40 + ca), Ah + ga);
            cpasync16(smem_u32(sAl + buf * 5120 + ra * 40 + ca), Al + ga);
            const int rb = c >> 4, cb = (c & 15) * 8;   // B: k row, n-elem offset
            const size_t gb = (size_t)(k0 + rb) * ldb + nb + cb;
            cpasync16(smem_u32(sBh + buf * 4352 + rb * 136 + cb), Bh + gb);
            cpasync16(smem_u32(sBl + buf * 4352 + rb * 136 + cb), Bl + gb);
        }
        cp_commit();
    };

    // ldmatrix lane mapping
    const int arf = lane & 15;                          // A row within m16
    const int acf = (lane >> 4) << 3;                   // A k offset (0/8)
    const int brf = (lane & 7) + ((lane >> 3) & 1) * 8; // B k row within k16
    const int bnf = (lane >> 4) << 3;                   // B n offset (0/8)

    issue(0, 0);
    cp_wait0();
    __syncthreads();

    const int nStages = kTotal >> 5;
    int buf = 0;
    for (int s = 0; s < nStages; s++) {
        if (s + 1 < nStages) issue(buf ^ 1, (s + 1) * 32);

        const int bufA = buf * 5120;
        const int bufB = buf * 4352;
#pragma unroll
        for (int kk = 0; kk < 2; kk++) {
            const int kc = kk * 16;
            uint32_t ah[2][4], al[2][4];
#pragma unroll
            for (int mi = 0; mi < 2; mi++) {
                int r = mw + mi * 16 + arf;
                ldsm4(ah[mi], smem_u32(sAh + bufA + r * 40 + kc + acf));
                ldsm4(al[mi], smem_u32(sAl + bufA + r * 40 + kc + acf));
            }
#pragma unroll
            for (int ng = 0; ng < 4; ng++) {
                int kr = kc + brf;
                int nc = nw + ng * 16 + bnf;
                uint32_t bh[4], bl[4];
                ldsm4t(bh, smem_u32(sBh + bufB + kr * 136 + nc));
                ldsm4t(bl, smem_u32(sBl + bufB + kr * 136 + nc));
#pragma unroll
                for (int mi = 0; mi < 2; mi++) {
#pragma unroll
                    for (int nj = 0; nj < 2; nj++) {
                        mma16816(acc[mi][ng * 2 + nj], ah[mi], bh[nj * 2], bh[nj * 2 + 1]);
                        mma16816(acc[mi][ng * 2 + nj], ah[mi], bl[nj * 2], bl[nj * 2 + 1]);
                        mma16816(acc[mi][ng * 2 + nj], al[mi], bh[nj * 2], bh[nj * 2 + 1]);
                    }
                }
            }
        }

        cp_wait0();
        __syncthreads();
        buf ^= 1;
    }

    // epilogue
#pragma unroll
    for (int mi = 0; mi < 2; mi++) {
#pragma unroll
        for (int ni = 0; ni < 8; ni++) {
            int row = m0 + mw + mi * 16 + (lane >> 2);
            int col = ncBase + nw + ni * 8 + (lane & 3) * 2;
            float2 c01 = {acc[mi][ni][0], acc[mi][ni][1]};
            float2 c23 = {acc[mi][ni][2], acc[mi][ni][3]};
            *(float2*)&C[(size_t)row * ldc + col]       = c01;
            *(float2*)&C[(size_t)(row + 8) * ldc + col] = c23;
        }
    }
}

// QKV: grid (24, 16). Column tiles: [0,2048)=q, [2048,2560)=k, [2560,3072)=v
__global__ void __launch_bounds__(256) qkv_gemm_tc() {
    const int n0 = blockIdx.x * 128;
    float* C;
    int ldc, ncb;
    if (n0 < 2048)      { C = g_q; ldc = 2048; ncb = n0;        }
    else if (n0 < 2560) { C = g_k; ldc = 512;  ncb = n0 - 2048; }
    else                { C = g_v; ldc = 512;  ncb = n0 - 2560; }
    gemm_core(g_Ah, g_Al, 4096, g_Bh, g_Bl, 3072, n0, C, ldc, ncb, 4096);
}

// out = g_o @ Wo : grid (16, 16)
__global__ void __launch_bounds__(256) out_gemm_tc(float* __restrict__ out) {
    const int n0 = blockIdx.x * 128;
    gemm_core(g_Oh, g_Ol, 2048, g_Wh, g_Wl, 2048, n0, out, 2048, n0, 2048);
}

// ============================================================================
// RoPE tables (double precision, tiny)
// ============================================================================
__global__ void rope_table_kernel(const int* __restrict__ positions)
{
    int idx = blockIdx.x * blockDim.x + threadIdx.x;   // t*32 + i
    if (idx >= T_TOK * 32) return;
    int t = idx >> 5;
    int i = idx & 31;
    double invf = pow(10000.0, -(double)i / 32.0);
    double fd   = (double)positions[t] * invf;
    g_cos[idx] = (float)cos(fd);
    g_sin[idx] = (float)sin(fd);
}

// ============================================================================
// Fused RMSNorm + RoPE (one warp per (token, head))
// ============================================================================
__global__ void norm_rope_kernel(const float* __restrict__ qw,
                                 const float* __restrict__ kw)
{
    int warpId = blockIdx.x * (blockDim.x >> 5) + (threadIdx.x >> 5);
    int lane   = threadIdx.x & 31;
    if (warpId >= T_TOK * (NH + NKV)) return;
    int t  = warpId / (NH + NKV);
    int hh = warpId % (NH + NKV);

    float* buf;
    int ld, col;
    const float* w;
    if (hh < NH) { buf = g_q; ld = NH * HD;  col = hh * HD;        w = qw; }
    else         { buf = g_k; ld = NKV * HD; col = (hh - NH) * HD; w = kw; }

    float x0 = buf[(size_t)t * ld + col + lane];
    float x1 = buf[(size_t)t * ld + col + 32 + lane];
    float ss = x0 * x0 + x1 * x1;
#pragma unroll
    for (int o = 16; o > 0; o >>= 1) ss += __shfl_xor_sync(0xffffffff, ss, o);
    float inv = rsqrtf(ss * (1.0f / 64.0f) + EPSV);
    x0 *= inv * w[lane];
    x1 *= inv * w[lane + 32];

    float c = g_cos[t * 32 + lane];
    float s = g_sin[t * 32 + lane];
    buf[(size_t)t * ld + col + lane]      = x0 * c - x1 * s;
    buf[(size_t)t * ld + col + 32 + lane] = x1 * c + x0 * s;
}

// ============================================================================
// Causal flash attention (unchanged — known good)
// ============================================================================
#define PLD 68
#define FLASH_SMEM (4 * 64 * PLD * (int)sizeof(float))

__global__ void __launch_bounds__(256) flash_kernel()
{
    extern __shared__ float sm[];
    float* Qt = sm;
    float* Kt = sm + 64 * PLD;
    float* Vs = sm + 2 * 64 * PLD;
    float* Pt = sm + 3 * 64 * PLD;

    const int qt  = blockIdx.x;
    const int h   = blockIdx.y;
    const int kvh = h >> 2;
    const int t   = threadIdx.x;
    const int tx  = t & 15;
    const int ty  = t >> 4;
    const int q0  = qt * 64;

#pragma unroll
    for (int u = 0; u < 4; u++) {
        int idx = u * 256 + t;
        int r = idx >> 4, cq = (idx & 15) * 4;
        float4 q4 = *(const float4*)&g_q[(size_t)(q0 + r) * (NH * HD) + h * HD + cq];
        Qt[(cq + 0) * PLD + r] = q4.x;
        Qt[(cq + 1) * PLD + r] = q4.y;
        Qt[(cq + 2) * PLD + r] = q4.z;
        Qt[(cq + 3) * PLD + r] = q4.w;
    }

    float acc[4][4];
    float m[4], l[4];
#pragma unroll
    for (int i = 0; i < 4; i++) {
        m[i] = -1e30f; l[i] = 0.0f;
#pragma unroll
        for (int j = 0; j < 4; j++) acc[i][j] = 0.0f;
    }

    __syncthreads();

    for (int kt = 0; kt <= qt; kt++) {
#pragma unroll
        for (int u = 0; u < 4; u++) {
            int idx = u * 256 + t;
            int r = idx >> 4, cq = (idx & 15) * 4;
            size_t gi = (size_t)(kt * 64 + r) * (NKV * HD) + kvh * HD + cq;
            float4 k4 = *(const float4*)&g_k[gi];
            float4 v4 = *(const float4*)&g_v[gi];
            Kt[(cq + 0) * PLD + r] = k4.x;
            Kt[(cq + 1) * PLD + r] = k4.y;
            Kt[(cq + 2) * PLD + r] = k4.z;
            Kt[(cq + 3) * PLD + r] = k4.w;
            *(float4*)&Vs[r * PLD + cq] = v4;
        }
        __syncthreads();

        float s[4][4];
#pragma unroll
        for (int i = 0; i < 4; i++)
#pragma unroll
            for (int j = 0; j < 4; j++) s[i][j] = 0.0f;

#pragma unroll 8
        for (int d = 0; d < 64; d++) {
            float4 av = *(const float4*)&Qt[d * PLD + ty * 4];
            float4 bv = *(const float4*)&Kt[d * PLD + tx * 4];
            float a[4] = {av.x, av.y, av.z, av.w};
            float b[4] = {bv.x, bv.y, bv.z, bv.w};
#pragma unroll
            for (int i = 0; i < 4; i++)
#pragma unroll
                for (int j = 0; j < 4; j++)
                    s[i][j] = fmaf(a[i], b[j], s[i][j]);
        }

        const bool diag = (kt == qt);
#pragma unroll
        for (int i = 0; i < 4; i++)
#pragma unroll
            for (int j = 0; j < 4; j++) {
                float v = s[i][j] * SM_SCALE;
                if (diag && (tx * 4 + j) > (ty * 4 + i)) v = -1e30f;
                s[i][j] = v;
            }

#pragma unroll
        for (int i = 0; i < 4; i++) {
            float rmax = fmaxf(fmaxf(s[i][0], s[i][1]), fmaxf(s[i][2], s[i][3]));
#pragma unroll
            for (int o = 8; o > 0; o >>= 1)
                rmax = fmaxf(rmax, __shfl_xor_sync(0xffffffff, rmax, o));
            float mnew  = fmaxf(m[i], rmax);
            float alpha = __expf(m[i] - mnew);
            m[i] = mnew;
            float rsum = 0.0f;
#pragma unroll
            for (int j = 0; j < 4; j++) {
                float p = __expf(s[i][j] - mnew);
                s[i][j] = p;
                rsum += p;
            }
#pragma unroll
            for (int o = 8; o > 0; o >>= 1)
                rsum += __shfl_xor_sync(0xffffffff, rsum, o);
            l[i] = l[i] * alpha + rsum;
#pragma unroll
            for (int j = 0; j < 4; j++) acc[i][j] *= alpha;
        }

#pragma unroll
        for (int j = 0; j < 4; j++) {
            float4 pc = {s[0][j], s[1][j], s[2][j], s[3][j]};
            *(float4*)&Pt[(tx * 4 + j) * PLD + ty * 4] = pc;
        }
        __syncthreads();

#pragma unroll 8
        for (int kk = 0; kk < 64; kk++) {
            float4 pv = *(const float4*)&Pt[kk * PLD + ty * 4];
            float4 vv = *(const float4*)&Vs[kk * PLD + tx * 4];
            float p[4] = {pv.x, pv.y, pv.z, pv.w};
            float v[4] = {vv.x, vv.y, vv.z, vv.w};
#pragma unroll
            for (int i = 0; i < 4; i++)
#pragma unroll
                for (int j = 0; j < 4; j++)
                    acc[i][j] = fmaf(p[i], v[j], acc[i][j]);
        }
        __syncthreads();
    }

#pragma unroll
    for (int i = 0; i < 4; i++) {
        float inv = 1.0f / l[i];
        float4 c = {acc[i][0] * inv, acc[i][1] * inv, acc[i][2] * inv, acc[i][3] * inv};
        *(float4*)&g_o[(size_t)(q0 + ty * 4 + i) * (NH * HD) + h * HD + tx * 4] = c;
    }
}

// ============================================================================
// launch
// ============================================================================
extern "C" void kernel_launch(void* const* d_in, const int* in_sizes, int n_in,
                              void* d_out, int out_size)
{
    const float* hidden = (const float*)d_in[0];
    const float* mu     = (const float*)d_in[1];
    const float* Wq     = (const float*)d_in[2];
    const float* Wk     = (const float*)d_in[3];
    const float* Wv     = (const float*)d_in[4];
    const float* Wo     = (const float*)d_in[5];
    const float* Wmq    = (const float*)d_in[6];
    const float* Wmk    = (const float*)d_in[7];
    const float* Wmv    = (const float*)d_in[8];
    const float* qnw    = (const float*)d_in[9];
    const float* knw    = (const float*)d_in[10];
    const int*   pos    = (const int*)d_in[11];
    float* out          = (float*)d_out;

    cudaFuncSetAttribute(flash_kernel, cudaFuncAttributeMaxDynamicSharedMemorySize, FLASH_SMEM);
    cudaFuncSetAttribute(qkv_gemm_tc, cudaFuncAttributeMaxDynamicSharedMemorySize, SMEM_GEMM_BYTES);
    cudaFuncSetAttribute(out_gemm_tc, cudaFuncAttributeMaxDynamicSharedMemorySize, SMEM_GEMM_BYTES);

    // bf16 split conversions
    convert_A_kernel<<<(T_TOK * 1024 + 255) / 256, 256>>>(hidden, mu);
    convert_B_kernel<<<(4096 * 768 + 255) / 256, 256>>>(Wq, Wk, Wv, Wmq, Wmk, Wmv);
    convert_Wo_kernel<<<(2048 * 512 + 255) / 256, 256>>>(Wo);

    // QKV projection on tensor cores
    qkv_gemm_tc<<<dim3(24, 16), 256, SMEM_GEMM_BYTES>>>();

    // RoPE tables + RMSNorm/RoPE
    rope_table_kernel<<<(T_TOK * 32 + 255) / 256, 256>>>(pos);
    norm_rope_kernel<<<(T_TOK * (NH + NKV) + 7) / 8, 256>>>(qnw, knw);

    // causal flash attention
    flash_kernel<<<dim3(T_TOK / 64, NH), 256, FLASH_SMEM>>>();

    // output projection on tensor cores
    convert_O_kernel<<<(2048 * 512 + 255) / 256, 256>>>();
    out_gemm_tc<<<dim3(16, 16), 256, SMEM_GEMM_BYTES>>>(out);
}

// round 8
// speedup vs baseline: 4.6353x; 1.5519x over previous
#include <cuda_runtime.h>
#include <cuda_bf16.h>
#include <math.h>
#include <stdint.h>

// ---------------- problem constants ----------------
#define T_TOK 2048
#define HID   2048
#define NH    32
#define NKV   8
#define HD    64
#define EPSV  1e-6f
#define SM_SCALE 0.125f

// ---------------- fp32 scratch ----------------
__device__ float g_q[T_TOK * NH * HD];     // [2048, 2048] (pre-norm QKV output)
__device__ float g_k[T_TOK * NKV * HD];    // [2048, 512]
__device__ float g_v[T_TOK * NKV * HD];    // [2048, 512]
__device__ float g_cos[T_TOK * (HD / 2)];
__device__ float g_sin[T_TOK * (HD / 2)];

// ---------------- bf16 split scratch ----------------
__device__ __nv_bfloat16 g_Ah[T_TOK * 4096];   // [2048,4096] = [hidden|mu] hi
__device__ __nv_bfloat16 g_Al[T_TOK * 4096];   // lo
__device__ __nv_bfloat16 g_Bh[4096 * 3072];    // [[Wq|Wk|Wv];[Wmq|Wmk|Wmv]] hi
__device__ __nv_bfloat16 g_Bl[4096 * 3072];
__device__ __nv_bfloat16 g_Oh[T_TOK * 2048];   // attention out hi/lo
__device__ __nv_bfloat16 g_Ol[T_TOK * 2048];
__device__ __nv_bfloat16 g_Wh[2048 * 2048];    // Wo hi/lo
__device__ __nv_bfloat16 g_Wl[2048 * 2048];
// flash operands (post norm+rope), bf16 hi/lo
__device__ __nv_bfloat16 g_qh[T_TOK * NH * HD];
__device__ __nv_bfloat16 g_ql[T_TOK * NH * HD];
__device__ __nv_bfloat16 g_kh[T_TOK * NKV * HD];
__device__ __nv_bfloat16 g_kl[T_TOK * NKV * HD];
__device__ __nv_bfloat16 g_vh[T_TOK * NKV * HD];
__device__ __nv_bfloat16 g_vl[T_TOK * NKV * HD];

// ============================================================================
// PTX helpers
// ============================================================================
__device__ __forceinline__ uint32_t smem_u32(const void* p) {
    return (uint32_t)__cvta_generic_to_shared(p);
}
__device__ __forceinline__ void ldsm4(uint32_t (&r)[4], uint32_t addr) {
    asm volatile("ldmatrix.sync.aligned.m8n8.x4.shared.b16 {%0,%1,%2,%3}, [%4];"
                 : "=r"(r[0]), "=r"(r[1]), "=r"(r[2]), "=r"(r[3]) : "r"(addr));
}
__device__ __forceinline__ void ldsm4t(uint32_t (&r)[4], uint32_t addr) {
    asm volatile("ldmatrix.sync.aligned.m8n8.x4.trans.shared.b16 {%0,%1,%2,%3}, [%4];"
                 : "=r"(r[0]), "=r"(r[1]), "=r"(r[2]), "=r"(r[3]) : "r"(addr));
}
__device__ __forceinline__ void mma16816(float (&c)[4], const uint32_t (&a)[4],
                                         uint32_t b0, uint32_t b1) {
    asm volatile("mma.sync.aligned.m16n8k16.row.col.f32.bf16.bf16.f32 "
                 "{%0,%1,%2,%3}, {%4,%5,%6,%7}, {%8,%9}, {%0,%1,%2,%3};"
                 : "+f"(c[0]), "+f"(c[1]), "+f"(c[2]), "+f"(c[3])
                 : "r"(a[0]), "r"(a[1]), "r"(a[2]), "r"(a[3]), "r"(b0), "r"(b1));
}
__device__ __forceinline__ void cpasync16(uint32_t dst, const void* src) {
    asm volatile("cp.async.cg.shared.global [%0], [%1], 16;" :: "r"(dst), "l"(src));
}
__device__ __forceinline__ void cp_commit() {
    asm volatile("cp.async.commit_group;" ::: "memory");
}
__device__ __forceinline__ void cp_wait0() {
    asm volatile("cp.async.wait_group 0;" ::: "memory");
}
__device__ __forceinline__ void cp_wait1() {
    asm volatile("cp.async.wait_group 1;" ::: "memory");
}

// ============================================================================
// bf16 split conversion helpers/kernels (x = hi + lo)
// ============================================================================
__device__ __forceinline__ uint32_t packh(__nv_bfloat16 a, __nv_bfloat16 b) {
    __nv_bfloat162 v = __halves2bfloat162(a, b);
    return *reinterpret_cast<uint32_t*>(&v);
}
__device__ __forceinline__ void split_store4(__nv_bfloat16* dh, __nv_bfloat16* dl,
                                             size_t off, float4 x) {
    __nv_bfloat16 h0 = __float2bfloat16(x.x);
    __nv_bfloat16 h1 = __float2bfloat16(x.y);
    __nv_bfloat16 h2 = __float2bfloat16(x.z);
    __nv_bfloat16 h3 = __float2bfloat16(x.w);
    __nv_bfloat16 l0 = __float2bfloat16(x.x - __bfloat162float(h0));
    __nv_bfloat16 l1 = __float2bfloat16(x.y - __bfloat162float(h1));
    __nv_bfloat16 l2 = __float2bfloat16(x.z - __bfloat162float(h2));
    __nv_bfloat16 l3 = __float2bfloat16(x.w - __bfloat162float(h3));
    uint2 hv = {packh(h0, h1), packh(h2, h3)};
    uint2 lv = {packh(l0, l1), packh(l2, l3)};
    *reinterpret_cast<uint2*>(dh + off) = hv;
    *reinterpret_cast<uint2*>(dl + off) = lv;
}

// A = [hidden | mu] : [2048, 4096]
__global__ void convert_A_kernel(const float* __restrict__ hidden,
                                 const float* __restrict__ mu) {
    int idx = blockIdx.x * blockDim.x + threadIdx.x;
    if (idx >= T_TOK * 1024) return;
    int t = idx >> 10, c4 = idx & 1023;
    float4 x = (c4 < 512) ? ((const float4*)hidden)[t * 512 + c4]
                          : ((const float4*)mu)[t * 512 + c4 - 512];
    split_store4(g_Ah, g_Al, (size_t)t * 4096 + c4 * 4, x);
}

// B : [4096, 3072]
__global__ void convert_B_kernel(const float* __restrict__ Wq, const float* __restrict__ Wk,
                                 const float* __restrict__ Wv, const float* __restrict__ Wmq,
                                 const float* __restrict__ Wmk, const float* __restrict__ Wmv) {
    int idx = blockIdx.x * blockDim.x + threadIdx.x;
    if (idx >= 4096 * 768) return;
    int k = idx / 768, c4 = idx % 768;
    int n = c4 * 4;
    int kk = k & 2047;
    const float* src;
    size_t off;
    if (n < 2048)      { src = (k < 2048) ? Wq : Wmq; off = (size_t)kk * 2048 + n; }
    else if (n < 2560) { src = (k < 2048) ? Wk : Wmk; off = (size_t)kk * 512 + (n - 2048); }
    else               { src = (k < 2048) ? Wv : Wmv; off = (size_t)kk * 512 + (n - 2560); }
    float4 x = *(const float4*)&src[off];
    split_store4(g_Bh, g_Bl, (size_t)k * 3072 + n, x);
}

__global__ void convert_Wo_kernel(const float* __restrict__ Wo) {
    int idx = blockIdx.x * blockDim.x + threadIdx.x;
    if (idx >= 2048 * 512) return;
    float4 x = ((const float4*)Wo)[idx];
    split_store4(g_Wh, g_Wl, (size_t)idx * 4, x);
}

__global__ void convert_V_kernel() {
    int idx = blockIdx.x * blockDim.x + threadIdx.x;
    if (idx >= 2048 * 128) return;   // 2048*512/4 float4s
    float4 x = ((const float4*)g_v)[idx];
    split_store4(g_vh, g_vl, (size_t)idx * 4, x);
}

// ============================================================================
// Tensor-core GEMM (unchanged, verified). Block 128x128, 8 warps.
// ============================================================================
#define SM_AH 0
#define SM_AL 10240
#define SM_BH 20480
#define SM_BL 29184
#define SMEM_GEMM_BYTES (37888 * 2)

__device__ __forceinline__ void gemm_core(
    const __nv_bfloat16* __restrict__ Ah, const __nv_bfloat16* __restrict__ Al, int lda,
    const __nv_bfloat16* __restrict__ Bh, const __nv_bfloat16* __restrict__ Bl, int ldb, int nb,
    float* __restrict__ C, int ldc, int ncBase, int kTotal)
{
    extern __shared__ __nv_bfloat16 smem[];
    __nv_bfloat16* sAh = smem + SM_AH;
    __nv_bfloat16* sAl = smem + SM_AL;
    __nv_bfloat16* sBh = smem + SM_BH;
    __nv_bfloat16* sBl = smem + SM_BL;

    const int t    = threadIdx.x;
    const int lane = t & 31;
    const int warp = t >> 5;
    const int mw   = (warp >> 1) * 32;
    const int nw   = (warp & 1) * 64;
    const int m0   = blockIdx.y * 128;

    float acc[2][8][4];
#pragma unroll
    for (int i = 0; i < 2; i++)
#pragma unroll
        for (int j = 0; j < 8; j++)
#pragma unroll
            for (int q = 0; q < 4; q++) acc[i][j][q] = 0.0f;

    auto issue = [&](int buf, int k0) {
#pragma unroll
        for (int i = 0; i < 2; i++) {
            const int c  = t + i * 256;
            const int ra = c >> 2, ca = (c & 3) * 8;
            const size_t ga = (size_t)(m0 + ra) * lda + k0 + ca;
            cpasync16(smem_u32(sAh + buf * 5120 + ra * 40 + ca), Ah + ga);
            cpasync16(smem_u32(sAl + buf * 5120 + ra * 40 + ca), Al + ga);
            const int rb = c >> 4, cb = (c & 15) * 8;
            const size_t gb = (size_t)(k0 + rb) * ldb + nb + cb;
            cpasync16(smem_u32(sBh + buf * 4352 + rb * 136 + cb), Bh + gb);
            cpasync16(smem_u32(sBl + buf * 4352 + rb * 136 + cb), Bl + gb);
        }
        cp_commit();
    };

    const int arf = lane & 15;
    const int acf = (lane >> 4) << 3;
    const int brf = (lane & 7) + ((lane >> 3) & 1) * 8;
    const int bnf = (lane >> 4) << 3;

    issue(0, 0);
    cp_wait0();
    __syncthreads();

    const int nStages = kTotal >> 5;
    int buf = 0;
    for (int s = 0; s < nStages; s++) {
        if (s + 1 < nStages) issue(buf ^ 1, (s + 1) * 32);

        const int bufA = buf * 5120;
        const int bufB = buf * 4352;
#pragma unroll
        for (int kk = 0; kk < 2; kk++) {
            const int kc = kk * 16;
            uint32_t ah[2][4], al[2][4];
#pragma unroll
            for (int mi = 0; mi < 2; mi++) {
                int r = mw + mi * 16 + arf;
                ldsm4(ah[mi], smem_u32(sAh + bufA + r * 40 + kc + acf));
                ldsm4(al[mi], smem_u32(sAl + bufA + r * 40 + kc + acf));
            }
#pragma unroll
            for (int ng = 0; ng < 4; ng++) {
                int kr = kc + brf;
                int nc = nw + ng * 16 + bnf;
                uint32_t bh[4], bl[4];
                ldsm4t(bh, smem_u32(sBh + bufB + kr * 136 + nc));
                ldsm4t(bl, smem_u32(sBl + bufB + kr * 136 + nc));
#pragma unroll
                for (int mi = 0; mi < 2; mi++) {
#pragma unroll
                    for (int nj = 0; nj < 2; nj++) {
                        mma16816(acc[mi][ng * 2 + nj], ah[mi], bh[nj * 2], bh[nj * 2 + 1]);
                        mma16816(acc[mi][ng * 2 + nj], ah[mi], bl[nj * 2], bl[nj * 2 + 1]);
                        mma16816(acc[mi][ng * 2 + nj], al[mi], bh[nj * 2], bh[nj * 2 + 1]);
                    }
                }
            }
        }

        cp_wait0();
        __syncthreads();
        buf ^= 1;
    }

#pragma unroll
    for (int mi = 0; mi < 2; mi++) {
#pragma unroll
        for (int ni = 0; ni < 8; ni++) {
            int row = m0 + mw + mi * 16 + (lane >> 2);
            int col = ncBase + nw + ni * 8 + (lane & 3) * 2;
            float2 c01 = {acc[mi][ni][0], acc[mi][ni][1]};
            float2 c23 = {acc[mi][ni][2], acc[mi][ni][3]};
            *(float2*)&C[(size_t)row * ldc + col]       = c01;
            *(float2*)&C[(size_t)(row + 8) * ldc + col] = c23;
        }
    }
}

__global__ void __launch_bounds__(256) qkv_gemm_tc() {
    const int n0 = blockIdx.x * 128;
    float* C;
    int ldc, ncb;
    if (n0 < 2048)      { C = g_q; ldc = 2048; ncb = n0;        }
    else if (n0 < 2560) { C = g_k; ldc = 512;  ncb = n0 - 2048; }
    else                { C = g_v; ldc = 512;  ncb = n0 - 2560; }
    gemm_core(g_Ah, g_Al, 4096, g_Bh, g_Bl, 3072, n0, C, ldc, ncb, 4096);
}

__global__ void __launch_bounds__(256) out_gemm_tc(float* __restrict__ out) {
    const int n0 = blockIdx.x * 128;
    gemm_core(g_Oh, g_Ol, 2048, g_Wh, g_Wl, 2048, n0, out, 2048, n0, 2048);
}

// ============================================================================
// RoPE tables (double precision, tiny)
// ============================================================================
__global__ void rope_table_kernel(const int* __restrict__ positions)
{
    int idx = blockIdx.x * blockDim.x + threadIdx.x;
    if (idx >= T_TOK * 32) return;
    int t = idx >> 5;
    int i = idx & 31;
    double invf = pow(10000.0, -(double)i / 32.0);
    double fd   = (double)positions[t] * invf;
    g_cos[idx] = (float)cos(fd);
    g_sin[idx] = (float)sin(fd);
}

// ============================================================================
// Fused RMSNorm + RoPE + bf16 hi/lo split (one warp per (token, head))
// ============================================================================
__global__ void norm_rope_kernel(const float* __restrict__ qw,
                                 const float* __restrict__ kw)
{
    int warpId = blockIdx.x * (blockDim.x >> 5) + (threadIdx.x >> 5);
    int lane   = threadIdx.x & 31;
    if (warpId >= T_TOK * (NH + NKV)) return;
    int t  = warpId / (NH + NKV);
    int hh = warpId % (NH + NKV);

    const float* buf;
    __nv_bfloat16 *dh, *dl;
    int ld, col;
    const float* w;
    if (hh < NH) { buf = g_q; dh = g_qh; dl = g_ql; ld = NH * HD;  col = hh * HD;        w = qw; }
    else         { buf = g_k; dh = g_kh; dl = g_kl; ld = NKV * HD; col = (hh - NH) * HD; w = kw; }

    size_t o0 = (size_t)t * ld + col + lane;
    size_t o1 = o0 + 32;
    float x0 = buf[o0];
    float x1 = buf[o1];
    float ss = x0 * x0 + x1 * x1;
#pragma unroll
    for (int o = 16; o > 0; o >>= 1) ss += __shfl_xor_sync(0xffffffff, ss, o);
    float inv = rsqrtf(ss * (1.0f / 64.0f) + EPSV);
    x0 *= inv * w[lane];
    x1 *= inv * w[lane + 32];

    float c = g_cos[t * 32 + lane];
    float s = g_sin[t * 32 + lane];
    float y0 = x0 * c - x1 * s;
    float y1 = x1 * c + x0 * s;

    __nv_bfloat16 h0 = __float2bfloat16(y0);
    __nv_bfloat16 h1 = __float2bfloat16(y1);
    dh[o0] = h0;
    dh[o1] = h1;
    dl[o0] = __float2bfloat16(y0 - __bfloat162float(h0));
    dl[o1] = __float2bfloat16(y1 - __bfloat162float(h1));
}

// ============================================================================
// Tensor-core causal flash attention.
// grid (32 q-tiles, 32 heads), block 128 (4 warps); warp = 16 q-rows x 64 keys.
// S = Qh Kh + Qh Kl + Ql Kh; P split hi/lo; O += Ph Vh + Ph Vl + Pl Vh.
// K tile natural [key][d] layout == col-major B operand -> plain ldmatrix.
// ============================================================================
#define FTS 72                      // smem row stride (bf16), 144B, conflict-free
#define FQH 0
#define FQL 4608
#define FKV_BASE 9216               // per-buf: Kh, Kl, Vh, Vl each 64*72=4608
#define FKV_SZ 18432
#define FLASH_SMEM ((FKV_BASE + 2 * FKV_SZ) * 2)   // 92160 bytes

__global__ void __launch_bounds__(128) flash_tc_kernel()
{
    extern __shared__ __nv_bfloat16 fsm[];
    const int qt   = blockIdx.x;
    const int h    = blockIdx.y;
    const int kvh  = h >> 2;
    const int t    = threadIdx.x;
    const int lane = t & 31;
    const int warp = t >> 5;
    const int mw   = warp * 16;
    const int q0   = qt * 64;

    // ---- async loads ----
    // Q: 64x64 hi+lo
#pragma unroll
    for (int i = 0; i < 4; i++) {
        int c = t + i * 128;
        int r = c >> 3, c8 = (c & 7) * 8;
        size_t g = (size_t)(q0 + r) * (NH * HD) + h * HD + c8;
        cpasync16(smem_u32(fsm + FQH + r * FTS + c8), g_qh + g);
        cpasync16(smem_u32(fsm + FQL + r * FTS + c8), g_ql + g);
    }
    auto issueKV = [&](int buf, int kt) {
        __nv_bfloat16* base = fsm + FKV_BASE + buf * FKV_SZ;
#pragma unroll
        for (int i = 0; i < 4; i++) {
            int c = t + i * 128;
            int r = c >> 3, c8 = (c & 7) * 8;
            size_t g = (size_t)(kt * 64 + r) * (NKV * HD) + kvh * HD + c8;
            cpasync16(smem_u32(base + r * FTS + c8),         g_kh + g);
            cpasync16(smem_u32(base + 4608 + r * FTS + c8),  g_kl + g);
            cpasync16(smem_u32(base + 9216 + r * FTS + c8),  g_vh + g);
            cpasync16(smem_u32(base + 13824 + r * FTS + c8), g_vl + g);
        }
        cp_commit();
    };
    issueKV(0, 0);   // Q chunks ride in this group too

    // fragment lane mappings
    const int arf = lane & 15;                     // A (Q/P rows)
    const int acf = (lane >> 4) << 3;
    const int krow = (lane & 7) + ((lane >> 4) << 3);   // K non-trans B rows (keys)
    const int kcol = ((lane >> 3) & 1) << 3;            // K d offset
    const int vkr = (lane & 7) + ((lane >> 3) & 1) * 8; // V trans B k rows (keys)
    const int vnc = (lane >> 4) << 3;                   // V n offset

    float mrow[2] = {-1e30f, -1e30f};
    float lrow[2] = {0.0f, 0.0f};
    float oa[8][4];
#pragma unroll
    for (int n = 0; n < 8; n++)
#pragma unroll
        for (int c = 0; c < 4; c++) oa[n][c] = 0.0f;

    uint32_t qfh[4][4], qfl[4][4];
    bool qloaded = false;

    int buf = 0;
    for (int kt = 0; kt <= qt; kt++) {
        if (kt < qt) { issueKV(buf ^ 1, kt + 1); cp_wait1(); }
        else         { cp_wait0(); }
        __syncthreads();

        if (!qloaded) {
#pragma unroll
            for (int ks = 0; ks < 4; ks++) {
                ldsm4(qfh[ks], smem_u32(fsm + FQH + (mw + arf) * FTS + ks * 16 + acf));
                ldsm4(qfl[ks], smem_u32(fsm + FQL + (mw + arf) * FTS + ks * 16 + acf));
            }
            qloaded = true;
        }

        __nv_bfloat16* sKh = fsm + FKV_BASE + buf * FKV_SZ;
        __nv_bfloat16* sKl = sKh + 4608;
        __nv_bfloat16* sVh = sKh + 9216;
        __nv_bfloat16* sVl = sKh + 13824;

        // ---- S = Q @ K^T ----
        float sc[8][4];
#pragma unroll
        for (int n = 0; n < 8; n++)
#pragma unroll
            for (int c = 0; c < 4; c++) sc[n][c] = 0.0f;

#pragma unroll
        for (int ks = 0; ks < 4; ks++) {
#pragma unroll
            for (int nt = 0; nt < 4; nt++) {
                uint32_t bh[4], bl[4];
                ldsm4(bh, smem_u32(sKh + (nt * 16 + krow) * FTS + ks * 16 + kcol));
                ldsm4(bl, smem_u32(sKl + (nt * 16 + krow) * FTS + ks * 16 + kcol));
                mma16816(sc[nt * 2],     qfh[ks], bh[0], bh[1]);
                mma16816(sc[nt * 2],     qfh[ks], bl[0], bl[1]);
                mma16816(sc[nt * 2],     qfl[ks], bh[0], bh[1]);
                mma16816(sc[nt * 2 + 1], qfh[ks], bh[2], bh[3]);
                mma16816(sc[nt * 2 + 1], qfh[ks], bl[2], bl[3]);
                mma16816(sc[nt * 2 + 1], qfl[ks], bh[2], bh[3]);
            }
        }

        // ---- scale + causal mask ----
        const int rl0 = mw + (lane >> 2);   // local q row of c0,c1
        if (kt == qt) {
#pragma unroll
            for (int n = 0; n < 8; n++) {
                int cl = n * 8 + (lane & 3) * 2;
                sc[n][0] = (cl     > rl0)     ? -1e30f : sc[n][0] * SM_SCALE;
                sc[n][1] = (cl + 1 > rl0)     ? -1e30f : sc[n][1] * SM_SCALE;
                sc[n][2] = (cl     > rl0 + 8) ? -1e30f : sc[n][2] * SM_SCALE;
                sc[n][3] = (cl + 1 > rl0 + 8) ? -1e30f : sc[n][3] * SM_SCALE;
            }
        } else {
#pragma unroll
            for (int n = 0; n < 8; n++)
#pragma unroll
                for (int c = 0; c < 4; c++) sc[n][c] *= SM_SCALE;
        }

        // ---- online softmax on fragments ----
        float tm0 = -1e30f, tm1 = -1e30f;
#pragma unroll
        for (int n = 0; n < 8; n++) {
            tm0 = fmaxf(tm0, fmaxf(sc[n][0], sc[n][1]));
            tm1 = fmaxf(tm1, fmaxf(sc[n][2], sc[n][3]));
        }
        tm0 = fmaxf(tm0, __shfl_xor_sync(0xffffffff, tm0, 1));
        tm0 = fmaxf(tm0, __shfl_xor_sync(0xffffffff, tm0, 2));
        tm1 = fmaxf(tm1, __shfl_xor_sync(0xffffffff, tm1, 1));
        tm1 = fmaxf(tm1, __shfl_xor_sync(0xffffffff, tm1, 2));

        float mn0 = fmaxf(mrow[0], tm0);
        float mn1 = fmaxf(mrow[1], tm1);
        float al0 = __expf(mrow[0] - mn0);
        float al1 = __expf(mrow[1] - mn1);
        mrow[0] = mn0; mrow[1] = mn1;

        float sum0 = 0.0f, sum1 = 0.0f;
#pragma unroll
        for (int n = 0; n < 8; n++) {
            sc[n][0] = __expf(sc[n][0] - mn0);
            sc[n][1] = __expf(sc[n][1] - mn0);
            sc[n][2] = __expf(sc[n][2] - mn1);
            sc[n][3] = __expf(sc[n][3] - mn1);
            sum0 += sc[n][0] + sc[n][1];
            sum1 += sc[n][2] + sc[n][3];
        }
        sum0 += __shfl_xor_sync(0xffffffff, sum0, 1);
        sum0 += __shfl_xor_sync(0xffffffff, sum0, 2);
        sum1 += __shfl_xor_sync(0xffffffff, sum1, 1);
        sum1 += __shfl_xor_sync(0xffffffff, sum1, 2);
        lrow[0] = lrow[0] * al0 + sum0;
        lrow[1] = lrow[1] * al1 + sum1;

#pragma unroll
        for (int n = 0; n < 8; n++) {
            oa[n][0] *= al0; oa[n][1] *= al0;
            oa[n][2] *= al1; oa[n][3] *= al1;
        }

        // ---- P fragments (C layout == A layout), hi/lo split ----
        uint32_t pfh[4][4], pfl[4][4];
#pragma unroll
        for (int ks = 0; ks < 4; ks++) {
#pragma unroll
            for (int half = 0; half < 2; half++) {       // 0: regs from sc[2ks], 1: sc[2ks+1]
                const float* pv = sc[2 * ks + half];
                __nv_bfloat16 h0 = __float2bfloat16(pv[0]);
                __nv_bfloat16 h1 = __float2bfloat16(pv[1]);
                __nv_bfloat16 h2 = __float2bfloat16(pv[2]);
                __nv_bfloat16 h3 = __float2bfloat16(pv[3]);
                pfh[ks][half * 2 + 0] = packh(h0, h1);
                pfh[ks][half * 2 + 1] = packh(h2, h3);
                pfl[ks][half * 2 + 0] = packh(__float2bfloat16(pv[0] - __bfloat162float(h0)),
                                              __float2bfloat16(pv[1] - __bfloat162float(h1)));
                pfl[ks][half * 2 + 1] = packh(__float2bfloat16(pv[2] - __bfloat162float(h2)),
                                              __float2bfloat16(pv[3] - __bfloat162float(h3)));
            }
        }
        // reorder: A frag = {row r k-lo, row r+8 k-lo, row r k-hi, row r+8 k-hi}
        // built above as: [0]=row r (sc[2ks][0,1]) [1]=row r+8 (sc[2ks][2,3])
        //                 [2]=row r (sc[2ks+1][0,1]) [3]=row r+8 (sc[2ks+1][2,3])  -- correct order already

        // ---- O += P @ V ----
#pragma unroll
        for (int ks = 0; ks < 4; ks++) {
#pragma unroll
            for (int nt = 0; nt < 4; nt++) {
                uint32_t vh[4], vl[4];
                ldsm4t(vh, smem_u32(sVh + (ks * 16 + vkr) * FTS + nt * 16 + vnc));
                ldsm4t(vl, smem_u32(sVl + (ks * 16 + vkr) * FTS + nt * 16 + vnc));
                mma16816(oa[nt * 2],     pfh[ks], vh[0], vh[1]);
                mma16816(oa[nt * 2],     pfh[ks], vl[0], vl[1]);
                mma16816(oa[nt * 2],     pfl[ks], vh[0], vh[1]);
                mma16816(oa[nt * 2 + 1], pfh[ks], vh[2], vh[3]);
                mma16816(oa[nt * 2 + 1], pfh[ks], vl[2], vl[3]);
                mma16816(oa[nt * 2 + 1], pfl[ks], vh[2], vh[3]);
            }
        }

        __syncthreads();
        buf ^= 1;
    }

    // ---- epilogue: normalize, split to bf16 hi/lo, store ----
    float inv0 = 1.0f / lrow[0];
    float inv1 = 1.0f / lrow[1];
    int row0 = q0 + mw + (lane >> 2);
#pragma unroll
    for (int n = 0; n < 8; n++) {
        int col = n * 8 + (lane & 3) * 2;
        float v0 = oa[n][0] * inv0, v1 = oa[n][1] * inv0;
        float v2 = oa[n][2] * inv1, v3 = oa[n][3] * inv1;
        size_t o0 = (size_t)row0 * (NH * HD) + h * HD + col;
        size_t o1 = (size_t)(row0 + 8) * (NH * HD) + h * HD + col;
        __nv_bfloat16 h0 = __float2bfloat16(v0), h1 = __float2bfloat16(v1);
        __nv_bfloat16 h2 = __float2bfloat16(v2), h3 = __float2bfloat16(v3);
        *(uint32_t*)&g_Oh[o0] = packh(h0, h1);
        *(uint32_t*)&g_Oh[o1] = packh(h2, h3);
        *(uint32_t*)&g_Ol[o0] = packh(__float2bfloat16(v0 - __bfloat162float(h0)),
                                      __float2bfloat16(v1 - __bfloat162float(h1)));
        *(uint32_t*)&g_Ol[o1] = packh(__float2bfloat16(v2 - __bfloat162float(h2)),
                                      __float2bfloat16(v3 - __bfloat162float(h3)));
    }
}

// ============================================================================
// launch
// ============================================================================
extern "C" void kernel_launch(void* const* d_in, const int* in_sizes, int n_in,
                              void* d_out, int out_size)
{
    const float* hidden = (const float*)d_in[0];
    const float* mu     = (const float*)d_in[1];
    const float* Wq     = (const float*)d_in[2];
    const float* Wk     = (const float*)d_in[3];
    const float* Wv     = (const float*)d_in[4];
    const float* Wo     = (const float*)d_in[5];
    const float* Wmq    = (const float*)d_in[6];
    const float* Wmk    = (const float*)d_in[7];
    const float* Wmv    = (const float*)d_in[8];
    const float* qnw    = (const float*)d_in[9];
    const float* knw    = (const float*)d_in[10];
    const int*   pos    = (const int*)d_in[11];
    float* out          = (float*)d_out;

    cudaFuncSetAttribute(qkv_gemm_tc, cudaFuncAttributeMaxDynamicSharedMemorySize, SMEM_GEMM_BYTES);
    cudaFuncSetAttribute(out_gemm_tc, cudaFuncAttributeMaxDynamicSharedMemorySize, SMEM_GEMM_BYTES);
    cudaFuncSetAttribute(flash_tc_kernel, cudaFuncAttributeMaxDynamicSharedMemorySize, FLASH_SMEM);

    // bf16 split conversions
    convert_A_kernel<<<(T_TOK * 1024 + 255) / 256, 256>>>(hidden, mu);
    convert_B_kernel<<<(4096 * 768 + 255) / 256, 256>>>(Wq, Wk, Wv, Wmq, Wmk, Wmv);
    convert_Wo_kernel<<<(2048 * 512 + 255) / 256, 256>>>(Wo);

    // QKV projection on tensor cores (fp32 out)
    qkv_gemm_tc<<<dim3(24, 16), 256, SMEM_GEMM_BYTES>>>();

    // RoPE tables + fused RMSNorm/RoPE/split
    rope_table_kernel<<<(T_TOK * 32 + 255) / 256, 256>>>(pos);
    norm_rope_kernel<<<(T_TOK * (NH + NKV) + 7) / 8, 256>>>(qnw, knw);
    convert_V_kernel<<<(2048 * 128 + 255) / 256, 256>>>();

    // tensor-core causal flash attention (writes O hi/lo splits directly)
    flash_tc_kernel<<<dim3(T_TOK / 64, NH), 128, FLASH_SMEM>>>();

    // output projection on tensor cores
    out_gemm_tc<<<dim3(16, 16), 256, SMEM_GEMM_BYTES>>>(out);
}